// round 2
// baseline (speedup 1.0000x reference)
#include <cuda_runtime.h>
#include <cstddef>

// ---------------- scratch (device globals; no allocation allowed) ----------------
__device__ float g_qh[2048 * 1024];
__device__ float g_tq[2048 * 1024];
__device__ float g_Q [2048 * 2048];
__device__ float g_kh[2048 * 256];
__device__ float g_tk[2048 * 256];
__device__ float g_K [2048 * 512];
__device__ float g_vh[2048 * 256];
__device__ float g_V [2048 * 512];
__device__ float g_O [2048 * 2048];

// ---------------- generic 128x128x8 SGEMM ----------------
// C[m,n] = sum_k A[m,k] * (TRANSB ? B[n,k] : B[k,n]) + bias[n]
// A: (M,K) row-major. TRANSB: B is (N,K) row-major. !TRANSB: B is (K,N) row-major.
// Requires M%128==0, N%128==0, K%8==0.
template <bool TRANSB>
__global__ __launch_bounds__(256) void sgemm_kernel(
    const float* __restrict__ A, const float* __restrict__ B,
    const float* __restrict__ bias, float* __restrict__ C,
    int M, int N, int K)
{
    __shared__ float As[8][128];
    __shared__ float Bs[8][128];
    const int tid = threadIdx.x;
    const int bm = blockIdx.y * 128;
    const int bn = blockIdx.x * 128;
    const int tx = tid & 15;   // -> n
    const int ty = tid >> 4;   // -> m

    float acc[8][8];
#pragma unroll
    for (int i = 0; i < 8; i++)
#pragma unroll
        for (int j = 0; j < 8; j++) acc[i][j] = 0.f;

    const int lr  = tid >> 1;         // 0..127 (row within tile)
    const int lk  = (tid & 1) * 4;    // 0 or 4 (k offset)
    const int nnr = tid >> 5;         // 0..7
    const int nnc = (tid & 31) * 4;   // 0..124

    for (int k0 = 0; k0 < K; k0 += 8) {
        float4 av = *(const float4*)(A + (size_t)(bm + lr) * K + k0 + lk);
        As[lk + 0][lr] = av.x;
        As[lk + 1][lr] = av.y;
        As[lk + 2][lr] = av.z;
        As[lk + 3][lr] = av.w;
        if (TRANSB) {
            float4 bv = *(const float4*)(B + (size_t)(bn + lr) * K + k0 + lk);
            Bs[lk + 0][lr] = bv.x;
            Bs[lk + 1][lr] = bv.y;
            Bs[lk + 2][lr] = bv.z;
            Bs[lk + 3][lr] = bv.w;
        } else {
            *(float4*)&Bs[nnr][nnc] =
                *(const float4*)(B + (size_t)(k0 + nnr) * N + bn + nnc);
        }
        __syncthreads();
#pragma unroll
        for (int kk = 0; kk < 8; kk++) {
            float4 a0 = *(const float4*)&As[kk][ty * 8];
            float4 a1 = *(const float4*)&As[kk][ty * 8 + 4];
            float4 b0 = *(const float4*)&Bs[kk][tx * 8];
            float4 b1 = *(const float4*)&Bs[kk][tx * 8 + 4];
            float af[8] = {a0.x, a0.y, a0.z, a0.w, a1.x, a1.y, a1.z, a1.w};
            float bf[8] = {b0.x, b0.y, b0.z, b0.w, b1.x, b1.y, b1.z, b1.w};
#pragma unroll
            for (int i = 0; i < 8; i++)
#pragma unroll
                for (int j = 0; j < 8; j++)
                    acc[i][j] = fmaf(af[i], bf[j], acc[i][j]);
        }
        __syncthreads();
    }

    float bv[8];
    if (bias) {
#pragma unroll
        for (int j = 0; j < 8; j++) bv[j] = bias[bn + tx * 8 + j];
    } else {
#pragma unroll
        for (int j = 0; j < 8; j++) bv[j] = 0.f;
    }
#pragma unroll
    for (int i = 0; i < 8; i++) {
        float* crow = C + (size_t)(bm + ty * 8 + i) * N + bn + tx * 8;
        float4 v0 = make_float4(acc[i][0] + bv[0], acc[i][1] + bv[1],
                                acc[i][2] + bv[2], acc[i][3] + bv[3]);
        float4 v1 = make_float4(acc[i][4] + bv[4], acc[i][5] + bv[5],
                                acc[i][6] + bv[6], acc[i][7] + bv[7]);
        *(float4*)crow = v0;
        *(float4*)(crow + 4) = v1;
    }
}

// ---------------- per-pair 2x2 rotation (HLA RoPE in low-rank space) ----------------
// x: (M, 2*halfD). Pair p = (2p, 2p+1) rotated by rot[s, p % 16] with s = token % S.
// u0 = t0*c + t1*s ; u1 = t1*c - t0*s   (rot stored [[c,-s],[s,c]])
__global__ void rotate_kernel(float* __restrict__ x, const float* __restrict__ rot,
                              int M, int halfD, int S)
{
    int idx = blockIdx.x * blockDim.x + threadIdx.x;
    if (idx >= M * halfD) return;
    int m = idx / halfD;
    int p = idx - m * halfD;
    int s = m % S;
    int h = p & 15;
    float4 r = ((const float4*)rot)[s * 16 + h];  // (c, -s, s, c)
    float c = r.x, sn = r.z;
    float* xp = x + (size_t)m * (halfD * 2) + 2 * p;
    float t0 = xp[0], t1 = xp[1];
    xp[0] = t0 * c + t1 * sn;
    xp[1] = t1 * c - t0 * sn;
}

// ---------------- copy first Nsrc columns of each row into dst ----------------
__global__ void copy_cols_kernel(const float* __restrict__ src, float* __restrict__ dst,
                                 int M, int Nsrc, int Ndst)
{
    int idx = blockIdx.x * blockDim.x + threadIdx.x;
    int per_row = Nsrc / 4;
    if (idx >= M * per_row) return;
    int m = idx / per_row;
    int c = idx - m * per_row;
    ((float4*)(dst + (size_t)m * Ndst))[c] = ((const float4*)(src + (size_t)m * Nsrc))[c];
}

// ---------------- causal GQA flash attention (fp32, 64x64 tiles) ----------------
// Q: (B,S,2048) head h at cols [64h,64h+64). K,V: (B,S,512), kv head h>>2.
// O: (B,S,2048) same layout as Q. Scores scaled by 0.125 = 64^-0.5.
#define ATT_SMEM_FLOATS (4 * 64 * 65 + 3 * 64)

__global__ __launch_bounds__(256) void attn_kernel(
    const float* __restrict__ Q, const float* __restrict__ Km,
    const float* __restrict__ Vm, float* __restrict__ O, int S)
{
    extern __shared__ float sm[];
    float (*Qs)[65] = (float(*)[65])sm;
    float (*Ks)[65] = (float(*)[65])(sm + 64 * 65);
    float (*Vs)[65] = (float(*)[65])(sm + 2 * 64 * 65);
    float (*Ss)[65] = (float(*)[65])(sm + 3 * 64 * 65);
    float* m_s     = sm + 4 * 64 * 65;
    float* l_s     = m_s + 64;
    float* alpha_s = l_s + 64;

    const int tid = threadIdx.x;
    const int tx = tid & 15, ty = tid >> 4;
    const int qt = blockIdx.x, h = blockIdx.y, b = blockIdx.z;
    const int hk = h >> 2;

    const float* qbase = Q + ((size_t)b * S + qt * 64) * 2048 + h * 64;
    for (int i = tid; i < 64 * 16; i += 256) {
        int r = i >> 4, c = (i & 15) * 4;
        float4 v = *(const float4*)(qbase + (size_t)r * 2048 + c);
        Qs[r][c + 0] = v.x * 0.125f;
        Qs[r][c + 1] = v.y * 0.125f;
        Qs[r][c + 2] = v.z * 0.125f;
        Qs[r][c + 3] = v.w * 0.125f;
    }
    if (tid < 64) { m_s[tid] = -1e30f; l_s[tid] = 0.f; }
    float o_acc[4][4];
#pragma unroll
    for (int i = 0; i < 4; i++)
#pragma unroll
        for (int j = 0; j < 4; j++) o_acc[i][j] = 0.f;
    __syncthreads();

    const float* kbase = Km + ((size_t)b * S) * 512 + hk * 64;
    const float* vbase = Vm + ((size_t)b * S) * 512 + hk * 64;

    for (int kt = 0; kt <= qt; kt++) {
        for (int i = tid; i < 64 * 16; i += 256) {
            int r = i >> 4, c = (i & 15) * 4;
            float4 kv = *(const float4*)(kbase + (size_t)(kt * 64 + r) * 512 + c);
            Ks[r][c + 0] = kv.x; Ks[r][c + 1] = kv.y;
            Ks[r][c + 2] = kv.z; Ks[r][c + 3] = kv.w;
            float4 vv = *(const float4*)(vbase + (size_t)(kt * 64 + r) * 512 + c);
            Vs[r][c + 0] = vv.x; Vs[r][c + 1] = vv.y;
            Vs[r][c + 2] = vv.z; Vs[r][c + 3] = vv.w;
        }
        __syncthreads();

        // S = Q K^T (4x4 per thread)
        float sacc[4][4];
#pragma unroll
        for (int i = 0; i < 4; i++)
#pragma unroll
            for (int j = 0; j < 4; j++) sacc[i][j] = 0.f;
#pragma unroll 8
        for (int d = 0; d < 64; d++) {
            float qv[4], kv[4];
#pragma unroll
            for (int i = 0; i < 4; i++) qv[i] = Qs[ty * 4 + i][d];
#pragma unroll
            for (int j = 0; j < 4; j++) kv[j] = Ks[tx * 4 + j][d];
#pragma unroll
            for (int i = 0; i < 4; i++)
#pragma unroll
                for (int j = 0; j < 4; j++)
                    sacc[i][j] = fmaf(qv[i], kv[j], sacc[i][j]);
        }
        if (kt == qt) {
#pragma unroll
            for (int i = 0; i < 4; i++)
#pragma unroll
                for (int j = 0; j < 4; j++)
                    if (tx * 4 + j > ty * 4 + i) sacc[i][j] = -1e30f;
        }
#pragma unroll
        for (int i = 0; i < 4; i++)
#pragma unroll
            for (int j = 0; j < 4; j++) Ss[ty * 4 + i][tx * 4 + j] = sacc[i][j];
        __syncthreads();

        // online softmax: 4 threads per row (16 cols each), shfl within 4-lane group
        {
            int row = tid >> 2, seg = tid & 3;
            int c0 = seg * 16;
            float mloc = -1e30f;
#pragma unroll
            for (int c = 0; c < 16; c++) mloc = fmaxf(mloc, Ss[row][c0 + c]);
            mloc = fmaxf(mloc, __shfl_xor_sync(0xffffffffu, mloc, 1));
            mloc = fmaxf(mloc, __shfl_xor_sync(0xffffffffu, mloc, 2));
            float mold = m_s[row];
            float mnew = fmaxf(mold, mloc);
            float lsum = 0.f;
#pragma unroll
            for (int c = 0; c < 16; c++) {
                float p = __expf(Ss[row][c0 + c] - mnew);
                Ss[row][c0 + c] = p;
                lsum += p;
            }
            lsum += __shfl_xor_sync(0xffffffffu, lsum, 1);
            lsum += __shfl_xor_sync(0xffffffffu, lsum, 2);
            if (seg == 0) {
                float alpha = __expf(mold - mnew);
                m_s[row] = mnew;
                l_s[row] = l_s[row] * alpha + lsum;
                alpha_s[row] = alpha;
            }
        }
        __syncthreads();

        // O = O*alpha + P V
#pragma unroll
        for (int i = 0; i < 4; i++) {
            float a = alpha_s[ty * 4 + i];
#pragma unroll
            for (int j = 0; j < 4; j++) o_acc[i][j] *= a;
        }
#pragma unroll 8
        for (int d = 0; d < 64; d++) {
            float pv[4], vv[4];
#pragma unroll
            for (int i = 0; i < 4; i++) pv[i] = Ss[ty * 4 + i][d];
#pragma unroll
            for (int j = 0; j < 4; j++) vv[j] = Vs[d][tx * 4 + j];
#pragma unroll
            for (int i = 0; i < 4; i++)
#pragma unroll
                for (int j = 0; j < 4; j++)
                    o_acc[i][j] = fmaf(pv[i], vv[j], o_acc[i][j]);
        }
        __syncthreads();
    }

    float* obase = O + ((size_t)b * S + qt * 64) * 2048 + h * 64;
#pragma unroll
    for (int i = 0; i < 4; i++) {
        float linv = 1.f / l_s[ty * 4 + i];
#pragma unroll
        for (int j = 0; j < 4; j++)
            obase[(size_t)(ty * 4 + i) * 2048 + tx * 4 + j] = o_acc[i][j] * linv;
    }
}

// ---------------- launch ----------------
static inline void gemmNT(const float* A, const float* B, const float* bias,
                          float* C, int M, int N, int K) {
    dim3 g(N / 128, M / 128);
    sgemm_kernel<true><<<g, 256>>>(A, B, bias, C, M, N, K);
}
static inline void gemmNN(const float* A, const float* B, const float* bias,
                          float* C, int M, int N, int K) {
    dim3 g(N / 128, M / 128);
    sgemm_kernel<false><<<g, 256>>>(A, B, bias, C, M, N, K);
}

extern "C" void kernel_launch(void* const* d_in, const int* in_sizes, int n_in,
                              void* d_out, int out_size)
{
    (void)n_in; (void)out_size;
    const float* X   = (const float*)d_in[0];
    const float* rot = (const float*)d_in[1];
    // d_in[2] = mask: exactly causal -> handled analytically in attn_kernel
    const float* Wqd = (const float*)d_in[3];
    const float* bqd = (const float*)d_in[4];
    const float* Wqu = (const float*)d_in[5];
    const float* bqu = (const float*)d_in[6];
    const float* Wkd = (const float*)d_in[7];
    const float* bkd = (const float*)d_in[8];
    const float* Wku = (const float*)d_in[9];
    const float* bku = (const float*)d_in[10];
    const float* Wvd = (const float*)d_in[11];
    const float* bvd = (const float*)d_in[12];
    const float* Wvu = (const float*)d_in[13];
    const float* bvu = (const float*)d_in[14];
    const float* Wo  = (const float*)d_in[15];
    const float* B_q = (const float*)d_in[16];
    const float* B_k = (const float*)d_in[17];
    const float* C_q = (const float*)d_in[18];
    const float* C_k = (const float*)d_in[19];
    float* out = (float*)d_out;

    const int S = in_sizes[1] / 64;          // rot is (S,16,2,2)
    const int M = in_sizes[0] / 2048;        // tokens = B*S
    const int Bb = M / S;

    float *qh, *tq, *Qb, *kh, *tk, *Kb, *vh, *Vb, *Ob;
    cudaGetSymbolAddress((void**)&qh, g_qh);
    cudaGetSymbolAddress((void**)&tq, g_tq);
    cudaGetSymbolAddress((void**)&Qb, g_Q);
    cudaGetSymbolAddress((void**)&kh, g_kh);
    cudaGetSymbolAddress((void**)&tk, g_tk);
    cudaGetSymbolAddress((void**)&Kb, g_K);
    cudaGetSymbolAddress((void**)&vh, g_vh);
    cudaGetSymbolAddress((void**)&Vb, g_V);
    cudaGetSymbolAddress((void**)&Ob, g_O);

    // ---- Q path ----
    gemmNT(X, Wqd, bqd, qh, M, 1024, 2048);                 // qh = X Wqd^T + b
    gemmNT(qh, B_q, nullptr, tq, M, 1024, 1024);            // t = qh B_q^T
    rotate_kernel<<<(M * 512 + 255) / 256, 256>>>(tq, rot, M, 512, S);
    gemmNN(tq, B_q, nullptr, qh, M, 1024, 1024);            // qh = u B_q
    gemmNT(qh, Wqu, bqu, Qb, M, 2048, 1024);                // Q = qh Wqu^T + b
    gemmNN(Qb, C_q, nullptr, tq, M, 1024, 2048);            // Qc = Q C_q
    copy_cols_kernel<<<(M * 256 + 255) / 256, 256>>>(tq, Qb, M, 1024, 2048);

    // ---- K path ----
    gemmNT(X, Wkd, bkd, kh, M, 256, 2048);
    gemmNT(kh, B_k, nullptr, tk, M, 256, 256);
    rotate_kernel<<<(M * 128 + 255) / 256, 256>>>(tk, rot, M, 128, S);
    gemmNN(tk, B_k, nullptr, kh, M, 256, 256);
    gemmNT(kh, Wku, bku, Kb, M, 512, 256);
    gemmNN(Kb, C_k, nullptr, tk, M, 256, 512);
    copy_cols_kernel<<<(M * 64 + 255) / 256, 256>>>(tk, Kb, M, 256, 512);

    // ---- V path ----
    gemmNT(X, Wvd, bvd, vh, M, 256, 2048);
    gemmNT(vh, Wvu, bvu, Vb, M, 512, 256);

    // ---- attention ----
    const int att_smem = ATT_SMEM_FLOATS * (int)sizeof(float);
    cudaFuncSetAttribute(attn_kernel, cudaFuncAttributeMaxDynamicSharedMemorySize, att_smem);
    attn_kernel<<<dim3(S / 64, 32, Bb), 256, att_smem>>>(Qb, Kb, Vb, Ob, S);

    // ---- output projection ----
    gemmNT(Ob, Wo, nullptr, out, M, 2048, 2048);
}

// round 4
// speedup vs baseline: 2.4673x; 2.4673x over previous
#include <cuda_runtime.h>
#include <cstdint>
#include <cstddef>

// ---------------- scratch (device globals; no allocation allowed) ----------------
__device__ float g_qh[2048 * 1024];
__device__ float g_tq[2048 * 1024];
__device__ float g_Q [2048 * 2048];
__device__ float g_kh[2048 * 256];
__device__ float g_tk[2048 * 256];
__device__ float g_K [2048 * 512];
__device__ float g_vh[2048 * 256];
__device__ float g_V [2048 * 512];
__device__ float g_O [2048 * 2048];

// ---------------- TF32 tensor-core GEMM ----------------
// C[m,n] = sum_k A[m,k] * (TRANSB ? B[n,k] : B[k,n]) + bias[n]
// Block tile 128x128, KT=32, 8 warps, warp tile 64x32 (4x4 m16n8k8 mma).
// Requires M%128==0, N%128==0, K%32==0.

__device__ __forceinline__ uint32_t cvt_tf32(float x) {
    uint32_t r;
    asm("cvt.rna.tf32.f32 %0, %1;" : "=r"(r) : "f"(x));
    return r;
}

__device__ __forceinline__ void mma_tf32(float* c, const uint32_t* a, const uint32_t* b) {
    asm volatile(
        "mma.sync.aligned.m16n8k8.row.col.f32.tf32.tf32.f32 "
        "{%0,%1,%2,%3}, {%4,%5,%6,%7}, {%8,%9}, {%0,%1,%2,%3};"
        : "+f"(c[0]), "+f"(c[1]), "+f"(c[2]), "+f"(c[3])
        : "r"(a[0]), "r"(a[1]), "r"(a[2]), "r"(a[3]), "r"(b[0]), "r"(b[1]));
}

#define KT   32
#define SPAD 36    // n-major row stride (floats): frag loads conflict-free
#define NPAD 132   // k-major row stride for the NN layout (float4-aligned)

template <bool TRANSB>
__global__ __launch_bounds__(256)
void tf32_gemm_kernel(const float* __restrict__ A, const float* __restrict__ B,
                      const float* __restrict__ bias, float* __restrict__ C,
                      int M, int N, int K)
{
    // As: [m][k] stride SPAD.
    // Bs: TRANSB -> nt[n][k] stride SPAD ; NN -> nn[k][n] stride NPAD.
    __shared__ uint32_t As[128][SPAD];
    __shared__ union {
        uint32_t nt[128][SPAD];   // 128 * 36 * 4 = 18432 B
        uint32_t nn[KT][NPAD];    //  32 * 132 * 4 = 16896 B
    } Bs;

    const int tid  = threadIdx.x;
    const int warp = tid >> 5, lane = tid & 31;
    const int gid  = lane >> 2, tig = lane & 3;
    const int bm = blockIdx.y * 128, bn = blockIdx.x * 128;
    const int wm = (warp >> 2) * 64;   // warp row offset (2 rows of warps)
    const int wn = (warp &  3) * 32;   // warp col offset (4 cols of warps)

    float acc[4][4][4];
#pragma unroll
    for (int mi = 0; mi < 4; mi++)
#pragma unroll
        for (int ni = 0; ni < 4; ni++)
#pragma unroll
            for (int r = 0; r < 4; r++) acc[mi][ni][r] = 0.f;

    for (int k0 = 0; k0 < K; k0 += KT) {
        // --- load A tile: 128x32 floats = 1024 float4, 4 per thread; cvt at store ---
#pragma unroll
        for (int i = 0; i < 4; i++) {
            int idx = tid + i * 256;
            int r = idx >> 3, c = (idx & 7) * 4;
            float4 v = *(const float4*)(A + (size_t)(bm + r) * K + k0 + c);
            uint4 u = make_uint4(cvt_tf32(v.x), cvt_tf32(v.y), cvt_tf32(v.z), cvt_tf32(v.w));
            *(uint4*)&As[r][c] = u;
        }
        // --- load B tile ---
        if (TRANSB) {
#pragma unroll
            for (int i = 0; i < 4; i++) {
                int idx = tid + i * 256;
                int r = idx >> 3, c = (idx & 7) * 4;
                float4 v = *(const float4*)(B + (size_t)(bn + r) * K + k0 + c);
                uint4 u = make_uint4(cvt_tf32(v.x), cvt_tf32(v.y), cvt_tf32(v.z), cvt_tf32(v.w));
                *(uint4*)&Bs.nt[r][c] = u;
            }
        } else {
            // B is (K,N): store as nn[k][n] (coalesced gmem + coalesced smem)
#pragma unroll
            for (int i = 0; i < 4; i++) {
                int idx = tid + i * 256;
                int k = idx >> 5, nq = (idx & 31) * 4;
                float4 v = *(const float4*)(B + (size_t)(k0 + k) * N + bn + nq);
                uint4 u = make_uint4(cvt_tf32(v.x), cvt_tf32(v.y), cvt_tf32(v.z), cvt_tf32(v.w));
                *(uint4*)&Bs.nn[k][nq] = u;
            }
        }
        __syncthreads();

#pragma unroll
        for (int k8 = 0; k8 < KT; k8 += 8) {
            uint32_t af[4][4], bf[4][2];
#pragma unroll
            for (int mi = 0; mi < 4; mi++) {
                int r0 = wm + mi * 16 + gid;
                af[mi][0] = As[r0    ][k8 + tig    ];
                af[mi][1] = As[r0 + 8][k8 + tig    ];
                af[mi][2] = As[r0    ][k8 + tig + 4];
                af[mi][3] = As[r0 + 8][k8 + tig + 4];
            }
#pragma unroll
            for (int ni = 0; ni < 4; ni++) {
                int n0 = wn + ni * 8 + gid;
                if (TRANSB) {
                    bf[ni][0] = Bs.nt[n0][k8 + tig    ];
                    bf[ni][1] = Bs.nt[n0][k8 + tig + 4];
                } else {
                    bf[ni][0] = Bs.nn[k8 + tig    ][n0];
                    bf[ni][1] = Bs.nn[k8 + tig + 4][n0];
                }
            }
#pragma unroll
            for (int mi = 0; mi < 4; mi++)
#pragma unroll
                for (int ni = 0; ni < 4; ni++)
                    mma_tf32(acc[mi][ni], af[mi], bf[ni]);
        }
        __syncthreads();
    }

    // --- epilogue: bias + store (float2 per mma row) ---
#pragma unroll
    for (int mi = 0; mi < 4; mi++) {
#pragma unroll
        for (int ni = 0; ni < 4; ni++) {
            int r = bm + wm + mi * 16 + gid;
            int c = bn + wn + ni * 8 + tig * 2;
            float b0 = 0.f, b1 = 0.f;
            if (bias) { b0 = bias[c]; b1 = bias[c + 1]; }
            float2 v0 = make_float2(acc[mi][ni][0] + b0, acc[mi][ni][1] + b1);
            float2 v1 = make_float2(acc[mi][ni][2] + b0, acc[mi][ni][3] + b1);
            *(float2*)(C + (size_t)r * N + c)       = v0;
            *(float2*)(C + (size_t)(r + 8) * N + c) = v1;
        }
    }
}

// ---------------- per-pair 2x2 rotation (HLA RoPE in low-rank space) ----------------
__global__ void rotate_kernel(float* __restrict__ x, const float* __restrict__ rot,
                              int M, int halfD, int S)
{
    int idx = blockIdx.x * blockDim.x + threadIdx.x;
    if (idx >= M * halfD) return;
    int m = idx / halfD;
    int p = idx - m * halfD;
    int s = m % S;
    int h = p & 15;
    float4 r = ((const float4*)rot)[s * 16 + h];  // (c, -s, s, c)
    float c = r.x, sn = r.z;
    float* xp = x + (size_t)m * (halfD * 2) + 2 * p;
    float t0 = xp[0], t1 = xp[1];
    xp[0] = t0 * c + t1 * sn;
    xp[1] = t1 * c - t0 * sn;
}

// ---------------- copy first Nsrc columns of each row into dst ----------------
__global__ void copy_cols_kernel(const float* __restrict__ src, float* __restrict__ dst,
                                 int M, int Nsrc, int Ndst)
{
    int idx = blockIdx.x * blockDim.x + threadIdx.x;
    int per_row = Nsrc / 4;
    if (idx >= M * per_row) return;
    int m = idx / per_row;
    int c = idx - m * per_row;
    ((float4*)(dst + (size_t)m * Ndst))[c] = ((const float4*)(src + (size_t)m * Nsrc))[c];
}

// ---------------- causal GQA flash attention (fp32, 64x64 tiles) ----------------
#define ATT_SMEM_FLOATS (4 * 64 * 65 + 3 * 64)

__global__ __launch_bounds__(256) void attn_kernel(
    const float* __restrict__ Q, const float* __restrict__ Km,
    const float* __restrict__ Vm, float* __restrict__ O, int S)
{
    extern __shared__ float sm[];
    float (*Qs)[65] = (float(*)[65])sm;
    float (*Ks)[65] = (float(*)[65])(sm + 64 * 65);
    float (*Vs)[65] = (float(*)[65])(sm + 2 * 64 * 65);
    float (*Ss)[65] = (float(*)[65])(sm + 3 * 64 * 65);
    float* m_s     = sm + 4 * 64 * 65;
    float* l_s     = m_s + 64;
    float* alpha_s = l_s + 64;

    const int tid = threadIdx.x;
    const int tx = tid & 15, ty = tid >> 4;
    const int qt = blockIdx.x, h = blockIdx.y, b = blockIdx.z;
    const int hk = h >> 2;

    const float* qbase = Q + ((size_t)b * S + qt * 64) * 2048 + h * 64;
    for (int i = tid; i < 64 * 16; i += 256) {
        int r = i >> 4, c = (i & 15) * 4;
        float4 v = *(const float4*)(qbase + (size_t)r * 2048 + c);
        Qs[r][c + 0] = v.x * 0.125f;
        Qs[r][c + 1] = v.y * 0.125f;
        Qs[r][c + 2] = v.z * 0.125f;
        Qs[r][c + 3] = v.w * 0.125f;
    }
    if (tid < 64) { m_s[tid] = -1e30f; l_s[tid] = 0.f; }
    float o_acc[4][4];
#pragma unroll
    for (int i = 0; i < 4; i++)
#pragma unroll
        for (int j = 0; j < 4; j++) o_acc[i][j] = 0.f;
    __syncthreads();

    const float* kbase = Km + ((size_t)b * S) * 512 + hk * 64;
    const float* vbase = Vm + ((size_t)b * S) * 512 + hk * 64;

    for (int kt = 0; kt <= qt; kt++) {
        for (int i = tid; i < 64 * 16; i += 256) {
            int r = i >> 4, c = (i & 15) * 4;
            float4 kv = *(const float4*)(kbase + (size_t)(kt * 64 + r) * 512 + c);
            Ks[r][c + 0] = kv.x; Ks[r][c + 1] = kv.y;
            Ks[r][c + 2] = kv.z; Ks[r][c + 3] = kv.w;
            float4 vv = *(const float4*)(vbase + (size_t)(kt * 64 + r) * 512 + c);
            Vs[r][c + 0] = vv.x; Vs[r][c + 1] = vv.y;
            Vs[r][c + 2] = vv.z; Vs[r][c + 3] = vv.w;
        }
        __syncthreads();

        float sacc[4][4];
#pragma unroll
        for (int i = 0; i < 4; i++)
#pragma unroll
            for (int j = 0; j < 4; j++) sacc[i][j] = 0.f;
#pragma unroll 8
        for (int d = 0; d < 64; d++) {
            float qv[4], kv[4];
#pragma unroll
            for (int i = 0; i < 4; i++) qv[i] = Qs[ty * 4 + i][d];
#pragma unroll
            for (int j = 0; j < 4; j++) kv[j] = Ks[tx * 4 + j][d];
#pragma unroll
            for (int i = 0; i < 4; i++)
#pragma unroll
                for (int j = 0; j < 4; j++)
                    sacc[i][j] = fmaf(qv[i], kv[j], sacc[i][j]);
        }
        if (kt == qt) {
#pragma unroll
            for (int i = 0; i < 4; i++)
#pragma unroll
                for (int j = 0; j < 4; j++)
                    if (tx * 4 + j > ty * 4 + i) sacc[i][j] = -1e30f;
        }
#pragma unroll
        for (int i = 0; i < 4; i++)
#pragma unroll
            for (int j = 0; j < 4; j++) Ss[ty * 4 + i][tx * 4 + j] = sacc[i][j];
        __syncthreads();

        {
            int row = tid >> 2, seg = tid & 3;
            int c0 = seg * 16;
            float mloc = -1e30f;
#pragma unroll
            for (int c = 0; c < 16; c++) mloc = fmaxf(mloc, Ss[row][c0 + c]);
            mloc = fmaxf(mloc, __shfl_xor_sync(0xffffffffu, mloc, 1));
            mloc = fmaxf(mloc, __shfl_xor_sync(0xffffffffu, mloc, 2));
            float mold = m_s[row];
            float mnew = fmaxf(mold, mloc);
            float lsum = 0.f;
#pragma unroll
            for (int c = 0; c < 16; c++) {
                float p = __expf(Ss[row][c0 + c] - mnew);
                Ss[row][c0 + c] = p;
                lsum += p;
            }
            lsum += __shfl_xor_sync(0xffffffffu, lsum, 1);
            lsum += __shfl_xor_sync(0xffffffffu, lsum, 2);
            if (seg == 0) {
                float alpha = __expf(mold - mnew);
                m_s[row] = mnew;
                l_s[row] = l_s[row] * alpha + lsum;
                alpha_s[row] = alpha;
            }
        }
        __syncthreads();

#pragma unroll
        for (int i = 0; i < 4; i++) {
            float a = alpha_s[ty * 4 + i];
#pragma unroll
            for (int j = 0; j < 4; j++) o_acc[i][j] *= a;
        }
#pragma unroll 8
        for (int d = 0; d < 64; d++) {
            float pv[4], vv[4];
#pragma unroll
            for (int i = 0; i < 4; i++) pv[i] = Ss[ty * 4 + i][d];
#pragma unroll
            for (int j = 0; j < 4; j++) vv[j] = Vs[d][tx * 4 + j];
#pragma unroll
            for (int i = 0; i < 4; i++)
#pragma unroll
                for (int j = 0; j < 4; j++)
                    o_acc[i][j] = fmaf(pv[i], vv[j], o_acc[i][j]);
        }
        __syncthreads();
    }

    float* obase = O + ((size_t)b * S + qt * 64) * 2048 + h * 64;
#pragma unroll
    for (int i = 0; i < 4; i++) {
        float linv = 1.f / l_s[ty * 4 + i];
#pragma unroll
        for (int j = 0; j < 4; j++)
            obase[(size_t)(ty * 4 + i) * 2048 + tx * 4 + j] = o_acc[i][j] * linv;
    }
}

// ---------------- launch helpers ----------------
static inline void gemmNT(const float* A, const float* B, const float* bias,
                          float* C, int M, int N, int K) {
    dim3 g(N / 128, M / 128);
    tf32_gemm_kernel<true><<<g, 256>>>(A, B, bias, C, M, N, K);
}
static inline void gemmNN(const float* A, const float* B, const float* bias,
                          float* C, int M, int N, int K) {
    dim3 g(N / 128, M / 128);
    tf32_gemm_kernel<false><<<g, 256>>>(A, B, bias, C, M, N, K);
}

extern "C" void kernel_launch(void* const* d_in, const int* in_sizes, int n_in,
                              void* d_out, int out_size)
{
    (void)n_in; (void)out_size;
    const float* X   = (const float*)d_in[0];
    const float* rot = (const float*)d_in[1];
    // d_in[2] = mask: exactly causal -> handled analytically in attn_kernel
    const float* Wqd = (const float*)d_in[3];
    const float* bqd = (const float*)d_in[4];
    const float* Wqu = (const float*)d_in[5];
    const float* bqu = (const float*)d_in[6];
    const float* Wkd = (const float*)d_in[7];
    const float* bkd = (const float*)d_in[8];
    const float* Wku = (const float*)d_in[9];
    const float* bku = (const float*)d_in[10];
    const float* Wvd = (const float*)d_in[11];
    const float* bvd = (const float*)d_in[12];
    const float* Wvu = (const float*)d_in[13];
    const float* bvu = (const float*)d_in[14];
    const float* Wo  = (const float*)d_in[15];
    const float* B_q = (const float*)d_in[16];
    const float* B_k = (const float*)d_in[17];
    const float* C_q = (const float*)d_in[18];
    const float* C_k = (const float*)d_in[19];
    float* out = (float*)d_out;

    const int S = in_sizes[1] / 64;          // rot is (S,16,2,2)
    const int M = in_sizes[0] / 2048;        // tokens = B*S
    const int Bb = M / S;

    float *qh, *tq, *Qb, *kh, *tk, *Kb, *vh, *Vb, *Ob;
    cudaGetSymbolAddress((void**)&qh, g_qh);
    cudaGetSymbolAddress((void**)&tq, g_tq);
    cudaGetSymbolAddress((void**)&Qb, g_Q);
    cudaGetSymbolAddress((void**)&kh, g_kh);
    cudaGetSymbolAddress((void**)&tk, g_tk);
    cudaGetSymbolAddress((void**)&Kb, g_K);
    cudaGetSymbolAddress((void**)&vh, g_vh);
    cudaGetSymbolAddress((void**)&Vb, g_V);
    cudaGetSymbolAddress((void**)&Ob, g_O);

    // ---- Q path ----
    gemmNT(X, Wqd, bqd, qh, M, 1024, 2048);                 // qh = X Wqd^T + b
    gemmNT(qh, B_q, nullptr, tq, M, 1024, 1024);            // t = qh B_q^T
    rotate_kernel<<<(M * 512 + 255) / 256, 256>>>(tq, rot, M, 512, S);
    gemmNN(tq, B_q, nullptr, qh, M, 1024, 1024);            // qh = u B_q
    gemmNT(qh, Wqu, bqu, Qb, M, 2048, 1024);                // Q = qh Wqu^T + b
    gemmNN(Qb, C_q, nullptr, tq, M, 1024, 2048);            // Qc = Q C_q
    copy_cols_kernel<<<(M * 256 + 255) / 256, 256>>>(tq, Qb, M, 1024, 2048);

    // ---- K path ----
    gemmNT(X, Wkd, bkd, kh, M, 256, 2048);
    gemmNT(kh, B_k, nullptr, tk, M, 256, 256);
    rotate_kernel<<<(M * 128 + 255) / 256, 256>>>(tk, rot, M, 128, S);
    gemmNN(tk, B_k, nullptr, kh, M, 256, 256);
    gemmNT(kh, Wku, bku, Kb, M, 512, 256);
    gemmNN(Kb, C_k, nullptr, tk, M, 256, 512);
    copy_cols_kernel<<<(M * 64 + 255) / 256, 256>>>(tk, Kb, M, 256, 512);

    // ---- V path ----
    gemmNT(X, Wvd, bvd, vh, M, 256, 2048);
    gemmNT(vh, Wvu, bvu, Vb, M, 512, 256);

    // ---- attention ----
    const int att_smem = ATT_SMEM_FLOATS * (int)sizeof(float);
    cudaFuncSetAttribute(attn_kernel, cudaFuncAttributeMaxDynamicSharedMemorySize, att_smem);
    attn_kernel<<<dim3(S / 64, 32, Bb), 256, att_smem>>>(Qb, Kb, Vb, Ob, S);

    // ---- output projection ----
    gemmNT(Ob, Wo, nullptr, out, M, 2048, 2048);
}

// round 7
// speedup vs baseline: 2.8539x; 1.1567x over previous
#include <cuda_runtime.h>
#include <cstdint>
#include <cstddef>

// ---------------- scratch (device globals; no allocation allowed) ----------------
__device__ float g_qh[2048 * 1024];
__device__ float g_tq[2048 * 1024];
__device__ float g_Q [2048 * 2048];
__device__ float g_kh[2048 * 256];
__device__ float g_tk[2048 * 256];
__device__ float g_K [2048 * 512];
__device__ float g_vh[2048 * 256];
__device__ float g_V [2048 * 512];
__device__ float g_O [2048 * 2048];

// ---------------- TF32 tensor-core GEMM (2-stage cp.async pipeline) ----------------
// C[m,n] = sum_k A[m,k] * (TRANSB ? B[n,k] : B[k,n]) + bias[n]
// Block tile 128x128, KT=32, 8 warps, warp tile 64x32 (4x4 m16n8k8 mma).
// Requires M%128==0, N%128==0, K%32==0.

__device__ __forceinline__ uint32_t cvt_tf32(float x) {
    uint32_t r;
    asm("cvt.rna.tf32.f32 %0, %1;" : "=r"(r) : "f"(x));
    return r;
}

__device__ __forceinline__ void mma_tf32(float* c, const uint32_t* a, const uint32_t* b) {
    asm volatile(
        "mma.sync.aligned.m16n8k8.row.col.f32.tf32.tf32.f32 "
        "{%0,%1,%2,%3}, {%4,%5,%6,%7}, {%8,%9}, {%0,%1,%2,%3};"
        : "+f"(c[0]), "+f"(c[1]), "+f"(c[2]), "+f"(c[3])
        : "r"(a[0]), "r"(a[1]), "r"(a[2]), "r"(a[3]), "r"(b[0]), "r"(b[1]));
}

__device__ __forceinline__ void cp_async16(uint32_t smem_dst, const void* gsrc) {
    asm volatile("cp.async.ca.shared.global [%0], [%1], 16;\n"
                 :: "r"(smem_dst), "l"(gsrc));
}
__device__ __forceinline__ void cp_commit() {
    asm volatile("cp.async.commit_group;\n");
}
template <int N>
__device__ __forceinline__ void cp_wait() {
    asm volatile("cp.async.wait_group %0;\n" :: "n"(N));
}

#define KT   32
#define SPAD 36    // n-major row stride (floats): frag loads conflict-free
#define NPAD 132   // k-major row stride for the NN layout (float4-aligned)
#define ASZ  (128 * SPAD)        // floats per A stage (4608)
#define BSZ  (128 * SPAD)        // floats per B stage (>= 32*NPAD = 4224)
#define STAGE (ASZ + BSZ)        // floats per pipeline stage
#define GEMM_SMEM_BYTES (2 * STAGE * 4)

// Tile loader: plain templated device function (no lambda, no pointer arrays).
// base = smem + s*STAGE; A tile at [0, ASZ), B tile at [ASZ, ASZ+BSZ).
template <bool TRANSB>
__device__ __forceinline__ void gemm_load_tiles(
    float* base, const float* A, const float* B,
    int bm, int bn, int k0, int K, int N,
    int lr, int lc, int lk, int ln)
{
    float* As = base;
    float* Bs = base + ASZ;
#pragma unroll
    for (int i = 0; i < 4; i++) {
        int r = lr + i * 32;
        uint32_t dst = (uint32_t)__cvta_generic_to_shared(As + r * SPAD + lc);
        cp_async16(dst, A + (size_t)(bm + r) * K + k0 + lc);
    }
    if (TRANSB) {
#pragma unroll
        for (int i = 0; i < 4; i++) {
            int r = lr + i * 32;
            uint32_t dst = (uint32_t)__cvta_generic_to_shared(Bs + r * SPAD + lc);
            cp_async16(dst, B + (size_t)(bn + r) * K + k0 + lc);
        }
    } else {
#pragma unroll
        for (int i = 0; i < 4; i++) {
            int k = lk + i * 8;
            uint32_t dst = (uint32_t)__cvta_generic_to_shared(Bs + k * NPAD + ln);
            cp_async16(dst, B + (size_t)(k0 + k) * N + bn + ln);
        }
    }
    cp_commit();
}

template <bool TRANSB>
__global__ __launch_bounds__(256)
void tf32_gemm_kernel(const float* __restrict__ A, const float* __restrict__ B,
                      const float* __restrict__ bias, float* __restrict__ C,
                      int M, int N, int K)
{
    extern __shared__ float smem[];

    const int tid  = threadIdx.x;
    const int warp = tid >> 5, lane = tid & 31;
    const int gid  = lane >> 2, tig = lane & 3;
    const int bm = blockIdx.y * 128, bn = blockIdx.x * 128;
    const int wm = (warp >> 2) * 64;   // warp row offset (2 rows of warps)
    const int wn = (warp &  3) * 32;   // warp col offset (4 cols of warps)

    // per-thread load coordinates (8-float rows -> 2 chunks of 4)
    const int lr = tid >> 3, lc = (tid & 7) * 4;            // A / NT-B: row, col
    const int lk = tid >> 5, ln = (tid & 31) * 4;           // NN-B: k, n

    float acc[4][4][4];
#pragma unroll
    for (int mi = 0; mi < 4; mi++)
#pragma unroll
        for (int ni = 0; ni < 4; ni++)
#pragma unroll
            for (int r = 0; r < 4; r++) acc[mi][ni][r] = 0.f;

    gemm_load_tiles<TRANSB>(smem, A, B, bm, bn, 0, K, N, lr, lc, lk, ln);

    int s = 0;
    for (int k0 = 0; k0 < K; k0 += KT, s ^= 1) {
        if (k0 + KT < K) {
            gemm_load_tiles<TRANSB>(smem + (s ^ 1) * STAGE, A, B,
                                    bm, bn, k0 + KT, K, N, lr, lc, lk, ln);
            cp_wait<1>();
        } else {
            cp_wait<0>();
        }
        __syncthreads();

        const float* As = smem + s * STAGE;
        const float* Bs = As + ASZ;
#pragma unroll
        for (int k8 = 0; k8 < KT; k8 += 8) {
            uint32_t af[4][4], bf[4][2];
#pragma unroll
            for (int mi = 0; mi < 4; mi++) {
                int r0 = wm + mi * 16 + gid;
                af[mi][0] = cvt_tf32(As[(r0    ) * SPAD + k8 + tig    ]);
                af[mi][1] = cvt_tf32(As[(r0 + 8) * SPAD + k8 + tig    ]);
                af[mi][2] = cvt_tf32(As[(r0    ) * SPAD + k8 + tig + 4]);
                af[mi][3] = cvt_tf32(As[(r0 + 8) * SPAD + k8 + tig + 4]);
            }
#pragma unroll
            for (int ni = 0; ni < 4; ni++) {
                int n0 = wn + ni * 8 + gid;
                if (TRANSB) {
                    bf[ni][0] = cvt_tf32(Bs[n0 * SPAD + k8 + tig    ]);
                    bf[ni][1] = cvt_tf32(Bs[n0 * SPAD + k8 + tig + 4]);
                } else {
                    bf[ni][0] = cvt_tf32(Bs[(k8 + tig    ) * NPAD + n0]);
                    bf[ni][1] = cvt_tf32(Bs[(k8 + tig + 4) * NPAD + n0]);
                }
            }
#pragma unroll
            for (int mi = 0; mi < 4; mi++)
#pragma unroll
                for (int ni = 0; ni < 4; ni++)
                    mma_tf32(acc[mi][ni], af[mi], bf[ni]);
        }
        __syncthreads();
    }

    // --- epilogue: bias + store (float2 per mma row) ---
#pragma unroll
    for (int mi = 0; mi < 4; mi++) {
#pragma unroll
        for (int ni = 0; ni < 4; ni++) {
            int r = bm + wm + mi * 16 + gid;
            int c = bn + wn + ni * 8 + tig * 2;
            float b0 = 0.f, b1 = 0.f;
            if (bias) { b0 = bias[c]; b1 = bias[c + 1]; }
            float2 v0 = make_float2(acc[mi][ni][0] + b0, acc[mi][ni][1] + b1);
            float2 v1 = make_float2(acc[mi][ni][2] + b0, acc[mi][ni][3] + b1);
            *(float2*)(C + (size_t)r * N + c)       = v0;
            *(float2*)(C + (size_t)(r + 8) * N + c) = v1;
        }
    }
}

// ---------------- per-pair 2x2 rotation (HLA RoPE in low-rank space) ----------------
__global__ void rotate_kernel(float* __restrict__ x, const float* __restrict__ rot,
                              int M, int halfD, int S)
{
    int idx = blockIdx.x * blockDim.x + threadIdx.x;
    if (idx >= M * halfD) return;
    int m = idx / halfD;
    int p = idx - m * halfD;
    int s = m % S;
    int h = p & 15;
    float4 r = ((const float4*)rot)[s * 16 + h];  // (c, -s, s, c)
    float c = r.x, sn = r.z;
    float* xp = x + (size_t)m * (halfD * 2) + 2 * p;
    float t0 = xp[0], t1 = xp[1];
    xp[0] = t0 * c + t1 * sn;
    xp[1] = t1 * c - t0 * sn;
}

// ---------------- copy first Nsrc columns of each row into dst ----------------
__global__ void copy_cols_kernel(const float* __restrict__ src, float* __restrict__ dst,
                                 int M, int Nsrc, int Ndst)
{
    int idx = blockIdx.x * blockDim.x + threadIdx.x;
    int per_row = Nsrc / 4;
    if (idx >= M * per_row) return;
    int m = idx / per_row;
    int c = idx - m * per_row;
    ((float4*)(dst + (size_t)m * Ndst))[c] = ((const float4*)(src + (size_t)m * Nsrc))[c];
}

// ---------------- causal GQA flash attention (fp32, 64x64 tiles) ----------------
#define ATT_SMEM_FLOATS (4 * 64 * 65 + 3 * 64)

__global__ __launch_bounds__(256) void attn_kernel(
    const float* __restrict__ Q, const float* __restrict__ Km,
    const float* __restrict__ Vm, float* __restrict__ O, int S)
{
    extern __shared__ float sm[];
    float (*Qs)[65] = (float(*)[65])sm;
    float (*Ks)[65] = (float(*)[65])(sm + 64 * 65);
    float (*Vs)[65] = (float(*)[65])(sm + 2 * 64 * 65);
    float (*Ss)[65] = (float(*)[65])(sm + 3 * 64 * 65);
    float* m_s     = sm + 4 * 64 * 65;
    float* l_s     = m_s + 64;
    float* alpha_s = l_s + 64;

    const int tid = threadIdx.x;
    const int tx = tid & 15, ty = tid >> 4;
    const int qt = blockIdx.x, h = blockIdx.y, b = blockIdx.z;
    const int hk = h >> 2;

    const float* qbase = Q + ((size_t)b * S + qt * 64) * 2048 + h * 64;
    for (int i = tid; i < 64 * 16; i += 256) {
        int r = i >> 4, c = (i & 15) * 4;
        float4 v = *(const float4*)(qbase + (size_t)r * 2048 + c);
        Qs[r][c + 0] = v.x * 0.125f;
        Qs[r][c + 1] = v.y * 0.125f;
        Qs[r][c + 2] = v.z * 0.125f;
        Qs[r][c + 3] = v.w * 0.125f;
    }
    if (tid < 64) { m_s[tid] = -1e30f; l_s[tid] = 0.f; }
    float o_acc[4][4];
#pragma unroll
    for (int i = 0; i < 4; i++)
#pragma unroll
        for (int j = 0; j < 4; j++) o_acc[i][j] = 0.f;
    __syncthreads();

    const float* kbase = Km + ((size_t)b * S) * 512 + hk * 64;
    const float* vbase = Vm + ((size_t)b * S) * 512 + hk * 64;

    for (int kt = 0; kt <= qt; kt++) {
        for (int i = tid; i < 64 * 16; i += 256) {
            int r = i >> 4, c = (i & 15) * 4;
            float4 kv = *(const float4*)(kbase + (size_t)(kt * 64 + r) * 512 + c);
            Ks[r][c + 0] = kv.x; Ks[r][c + 1] = kv.y;
            Ks[r][c + 2] = kv.z; Ks[r][c + 3] = kv.w;
            float4 vv = *(const float4*)(vbase + (size_t)(kt * 64 + r) * 512 + c);
            Vs[r][c + 0] = vv.x; Vs[r][c + 1] = vv.y;
            Vs[r][c + 2] = vv.z; Vs[r][c + 3] = vv.w;
        }
        __syncthreads();

        float sacc[4][4];
#pragma unroll
        for (int i = 0; i < 4; i++)
#pragma unroll
            for (int j = 0; j < 4; j++) sacc[i][j] = 0.f;
#pragma unroll 8
        for (int d = 0; d < 64; d++) {
            float qv[4], kv[4];
#pragma unroll
            for (int i = 0; i < 4; i++) qv[i] = Qs[ty * 4 + i][d];
#pragma unroll
            for (int j = 0; j < 4; j++) kv[j] = Ks[tx * 4 + j][d];
#pragma unroll
            for (int i = 0; i < 4; i++)
#pragma unroll
                for (int j = 0; j < 4; j++)
                    sacc[i][j] = fmaf(qv[i], kv[j], sacc[i][j]);
        }
        if (kt == qt) {
#pragma unroll
            for (int i = 0; i < 4; i++)
#pragma unroll
                for (int j = 0; j < 4; j++)
                    if (tx * 4 + j > ty * 4 + i) sacc[i][j] = -1e30f;
        }
#pragma unroll
        for (int i = 0; i < 4; i++)
#pragma unroll
            for (int j = 0; j < 4; j++) Ss[ty * 4 + i][tx * 4 + j] = sacc[i][j];
        __syncthreads();

        {
            int row = tid >> 2, seg = tid & 3;
            int c0 = seg * 16;
            float mloc = -1e30f;
#pragma unroll
            for (int c = 0; c < 16; c++) mloc = fmaxf(mloc, Ss[row][c0 + c]);
            mloc = fmaxf(mloc, __shfl_xor_sync(0xffffffffu, mloc, 1));
            mloc = fmaxf(mloc, __shfl_xor_sync(0xffffffffu, mloc, 2));
            float mold = m_s[row];
            float mnew = fmaxf(mold, mloc);
            float lsum = 0.f;
#pragma unroll
            for (int c = 0; c < 16; c++) {
                float p = __expf(Ss[row][c0 + c] - mnew);
                Ss[row][c0 + c] = p;
                lsum += p;
            }
            lsum += __shfl_xor_sync(0xffffffffu, lsum, 1);
            lsum += __shfl_xor_sync(0xffffffffu, lsum, 2);
            if (seg == 0) {
                float alpha = __expf(mold - mnew);
                m_s[row] = mnew;
                l_s[row] = l_s[row] * alpha + lsum;
                alpha_s[row] = alpha;
            }
        }
        __syncthreads();

#pragma unroll
        for (int i = 0; i < 4; i++) {
            float a = alpha_s[ty * 4 + i];
#pragma unroll
            for (int j = 0; j < 4; j++) o_acc[i][j] *= a;
        }
#pragma unroll 8
        for (int d = 0; d < 64; d++) {
            float pv[4], vv[4];
#pragma unroll
            for (int i = 0; i < 4; i++) pv[i] = Ss[ty * 4 + i][d];
#pragma unroll
            for (int j = 0; j < 4; j++) vv[j] = Vs[d][tx * 4 + j];
#pragma unroll
            for (int i = 0; i < 4; i++)
#pragma unroll
                for (int j = 0; j < 4; j++)
                    o_acc[i][j] = fmaf(pv[i], vv[j], o_acc[i][j]);
        }
        __syncthreads();
    }

    float* obase = O + ((size_t)b * S + qt * 64) * 2048 + h * 64;
#pragma unroll
    for (int i = 0; i < 4; i++) {
        float linv = 1.f / l_s[ty * 4 + i];
#pragma unroll
        for (int j = 0; j < 4; j++)
            obase[(size_t)(ty * 4 + i) * 2048 + tx * 4 + j] = o_acc[i][j] * linv;
    }
}

// ---------------- launch helpers ----------------
static inline void gemmNT(const float* A, const float* B, const float* bias,
                          float* C, int M, int N, int K) {
    dim3 g(N / 128, M / 128);
    cudaFuncSetAttribute(tf32_gemm_kernel<true>,
                         cudaFuncAttributeMaxDynamicSharedMemorySize, GEMM_SMEM_BYTES);
    tf32_gemm_kernel<true><<<g, 256, GEMM_SMEM_BYTES>>>(A, B, bias, C, M, N, K);
}
static inline void gemmNN(const float* A, const float* B, const float* bias,
                          float* C, int M, int N, int K) {
    dim3 g(N / 128, M / 128);
    cudaFuncSetAttribute(tf32_gemm_kernel<false>,
                         cudaFuncAttributeMaxDynamicSharedMemorySize, GEMM_SMEM_BYTES);
    tf32_gemm_kernel<false><<<g, 256, GEMM_SMEM_BYTES>>>(A, B, bias, C, M, N, K);
}

extern "C" void kernel_launch(void* const* d_in, const int* in_sizes, int n_in,
                              void* d_out, int out_size)
{
    (void)n_in; (void)out_size;
    const float* X   = (const float*)d_in[0];
    const float* rot = (const float*)d_in[1];
    // d_in[2] = mask: exactly causal -> handled analytically in attn_kernel
    const float* Wqd = (const float*)d_in[3];
    const float* bqd = (const float*)d_in[4];
    const float* Wqu = (const float*)d_in[5];
    const float* bqu = (const float*)d_in[6];
    const float* Wkd = (const float*)d_in[7];
    const float* bkd = (const float*)d_in[8];
    const float* Wku = (const float*)d_in[9];
    const float* bku = (const float*)d_in[10];
    const float* Wvd = (const float*)d_in[11];
    const float* bvd = (const float*)d_in[12];
    const float* Wvu = (const float*)d_in[13];
    const float* bvu = (const float*)d_in[14];
    const float* Wo  = (const float*)d_in[15];
    const float* B_q = (const float*)d_in[16];
    const float* B_k = (const float*)d_in[17];
    const float* C_q = (const float*)d_in[18];
    const float* C_k = (const float*)d_in[19];
    float* out = (float*)d_out;

    const int S = in_sizes[1] / 64;          // rot is (S,16,2,2)
    const int M = in_sizes[0] / 2048;        // tokens = B*S
    const int Bb = M / S;

    float *qh, *tq, *Qb, *kh, *tk, *Kb, *vh, *Vb, *Ob;
    cudaGetSymbolAddress((void**)&qh, g_qh);
    cudaGetSymbolAddress((void**)&tq, g_tq);
    cudaGetSymbolAddress((void**)&Qb, g_Q);
    cudaGetSymbolAddress((void**)&kh, g_kh);
    cudaGetSymbolAddress((void**)&tk, g_tk);
    cudaGetSymbolAddress((void**)&Kb, g_K);
    cudaGetSymbolAddress((void**)&vh, g_vh);
    cudaGetSymbolAddress((void**)&Vb, g_V);
    cudaGetSymbolAddress((void**)&Ob, g_O);

    // ---- Q path ----
    gemmNT(X, Wqd, bqd, qh, M, 1024, 2048);                 // qh = X Wqd^T + b
    gemmNT(qh, B_q, nullptr, tq, M, 1024, 1024);            // t = qh B_q^T
    rotate_kernel<<<(M * 512 + 255) / 256, 256>>>(tq, rot, M, 512, S);
    gemmNN(tq, B_q, nullptr, qh, M, 1024, 1024);            // qh = u B_q
    gemmNT(qh, Wqu, bqu, Qb, M, 2048, 1024);                // Q = qh Wqu^T + b
    gemmNN(Qb, C_q, nullptr, tq, M, 1024, 2048);            // Qc = Q C_q
    copy_cols_kernel<<<(M * 256 + 255) / 256, 256>>>(tq, Qb, M, 1024, 2048);

    // ---- K path ----
    gemmNT(X, Wkd, bkd, kh, M, 256, 2048);
    gemmNT(kh, B_k, nullptr, tk, M, 256, 256);
    rotate_kernel<<<(M * 128 + 255) / 256, 256>>>(tk, rot, M, 128, S);
    gemmNN(tk, B_k, nullptr, kh, M, 256, 256);
    gemmNT(kh, Wku, bku, Kb, M, 512, 256);
    gemmNN(Kb, C_k, nullptr, tk, M, 256, 512);
    copy_cols_kernel<<<(M * 64 + 255) / 256, 256>>>(tk, Kb, M, 256, 512);

    // ---- V path ----
    gemmNT(X, Wvd, bvd, vh, M, 256, 2048);
    gemmNT(vh, Wvu, bvu, Vb, M, 512, 256);

    // ---- attention ----
    const int att_smem = ATT_SMEM_FLOATS * (int)sizeof(float);
    cudaFuncSetAttribute(attn_kernel, cudaFuncAttributeMaxDynamicSharedMemorySize, att_smem);
    attn_kernel<<<dim3(S / 64, 32, Bb), 256, att_smem>>>(Qb, Kb, Vb, Ob, S);

    // ---- output projection ----
    gemmNT(Ob, Wo, nullptr, out, M, 2048, 2048);
}

// round 8
// speedup vs baseline: 3.6468x; 1.2778x over previous
#include <cuda_runtime.h>
#include <cstdint>
#include <cstddef>

// ---------------- scratch (device globals; no allocation allowed) ----------------
__device__ float g_qh[2048 * 1024];
__device__ float g_tq[2048 * 1024];
__device__ float g_Q [2048 * 2048];
__device__ float g_kh[2048 * 256];
__device__ float g_tk[2048 * 256];
__device__ float g_K [2048 * 512];
__device__ float g_vh[2048 * 256];
__device__ float g_V [2048 * 512];
__device__ float g_O [2048 * 2048];

// ---------------- shared PTX helpers ----------------
__device__ __forceinline__ uint32_t cvt_tf32(float x) {
    uint32_t r;
    asm("cvt.rna.tf32.f32 %0, %1;" : "=r"(r) : "f"(x));
    return r;
}

__device__ __forceinline__ void mma_tf32(float* c, const uint32_t* a, const uint32_t* b) {
    asm volatile(
        "mma.sync.aligned.m16n8k8.row.col.f32.tf32.tf32.f32 "
        "{%0,%1,%2,%3}, {%4,%5,%6,%7}, {%8,%9}, {%0,%1,%2,%3};"
        : "+f"(c[0]), "+f"(c[1]), "+f"(c[2]), "+f"(c[3])
        : "r"(a[0]), "r"(a[1]), "r"(a[2]), "r"(a[3]), "r"(b[0]), "r"(b[1]));
}

__device__ __forceinline__ void cp_async16(uint32_t smem_dst, const void* gsrc) {
    asm volatile("cp.async.ca.shared.global [%0], [%1], 16;\n"
                 :: "r"(smem_dst), "l"(gsrc));
}
__device__ __forceinline__ void cp_commit() {
    asm volatile("cp.async.commit_group;\n");
}
template <int N>
__device__ __forceinline__ void cp_wait() {
    asm volatile("cp.async.wait_group %0;\n" :: "n"(N));
}

// ---------------- TF32 tensor-core GEMM (2-stage cp.async pipeline) ----------------
#define KT   32
#define SPAD 36    // n-major row stride (floats): frag loads conflict-free
#define NPAD 132   // k-major row stride for the NN layout (float4-aligned)
#define ASZ  (128 * SPAD)
#define BSZ  (128 * SPAD)
#define STAGE (ASZ + BSZ)
#define GEMM_SMEM_BYTES (2 * STAGE * 4)

template <bool TRANSB>
__device__ __forceinline__ void gemm_load_tiles(
    float* base, const float* A, const float* B,
    int bm, int bn, int k0, int K, int N,
    int lr, int lc, int lk, int ln)
{
    float* As = base;
    float* Bs = base + ASZ;
#pragma unroll
    for (int i = 0; i < 4; i++) {
        int r = lr + i * 32;
        uint32_t dst = (uint32_t)__cvta_generic_to_shared(As + r * SPAD + lc);
        cp_async16(dst, A + (size_t)(bm + r) * K + k0 + lc);
    }
    if (TRANSB) {
#pragma unroll
        for (int i = 0; i < 4; i++) {
            int r = lr + i * 32;
            uint32_t dst = (uint32_t)__cvta_generic_to_shared(Bs + r * SPAD + lc);
            cp_async16(dst, B + (size_t)(bn + r) * K + k0 + lc);
        }
    } else {
#pragma unroll
        for (int i = 0; i < 4; i++) {
            int k = lk + i * 8;
            uint32_t dst = (uint32_t)__cvta_generic_to_shared(Bs + k * NPAD + ln);
            cp_async16(dst, B + (size_t)(k0 + k) * N + bn + ln);
        }
    }
    cp_commit();
}

template <bool TRANSB>
__global__ __launch_bounds__(256)
void tf32_gemm_kernel(const float* __restrict__ A, const float* __restrict__ B,
                      const float* __restrict__ bias, float* __restrict__ C,
                      int M, int N, int K)
{
    extern __shared__ float smem[];

    const int tid  = threadIdx.x;
    const int warp = tid >> 5, lane = tid & 31;
    const int gid  = lane >> 2, tig = lane & 3;
    const int bm = blockIdx.y * 128, bn = blockIdx.x * 128;
    const int wm = (warp >> 2) * 64;
    const int wn = (warp &  3) * 32;

    const int lr = tid >> 3, lc = (tid & 7) * 4;
    const int lk = tid >> 5, ln = (tid & 31) * 4;

    float acc[4][4][4];
#pragma unroll
    for (int mi = 0; mi < 4; mi++)
#pragma unroll
        for (int ni = 0; ni < 4; ni++)
#pragma unroll
            for (int r = 0; r < 4; r++) acc[mi][ni][r] = 0.f;

    gemm_load_tiles<TRANSB>(smem, A, B, bm, bn, 0, K, N, lr, lc, lk, ln);

    int s = 0;
    for (int k0 = 0; k0 < K; k0 += KT, s ^= 1) {
        if (k0 + KT < K) {
            gemm_load_tiles<TRANSB>(smem + (s ^ 1) * STAGE, A, B,
                                    bm, bn, k0 + KT, K, N, lr, lc, lk, ln);
            cp_wait<1>();
        } else {
            cp_wait<0>();
        }
        __syncthreads();

        const float* As = smem + s * STAGE;
        const float* Bs = As + ASZ;
#pragma unroll
        for (int k8 = 0; k8 < KT; k8 += 8) {
            uint32_t af[4][4], bf[4][2];
#pragma unroll
            for (int mi = 0; mi < 4; mi++) {
                int r0 = wm + mi * 16 + gid;
                af[mi][0] = cvt_tf32(As[(r0    ) * SPAD + k8 + tig    ]);
                af[mi][1] = cvt_tf32(As[(r0 + 8) * SPAD + k8 + tig    ]);
                af[mi][2] = cvt_tf32(As[(r0    ) * SPAD + k8 + tig + 4]);
                af[mi][3] = cvt_tf32(As[(r0 + 8) * SPAD + k8 + tig + 4]);
            }
#pragma unroll
            for (int ni = 0; ni < 4; ni++) {
                int n0 = wn + ni * 8 + gid;
                if (TRANSB) {
                    bf[ni][0] = cvt_tf32(Bs[n0 * SPAD + k8 + tig    ]);
                    bf[ni][1] = cvt_tf32(Bs[n0 * SPAD + k8 + tig + 4]);
                } else {
                    bf[ni][0] = cvt_tf32(Bs[(k8 + tig    ) * NPAD + n0]);
                    bf[ni][1] = cvt_tf32(Bs[(k8 + tig + 4) * NPAD + n0]);
                }
            }
#pragma unroll
            for (int mi = 0; mi < 4; mi++)
#pragma unroll
                for (int ni = 0; ni < 4; ni++)
                    mma_tf32(acc[mi][ni], af[mi], bf[ni]);
        }
        __syncthreads();
    }

#pragma unroll
    for (int mi = 0; mi < 4; mi++) {
#pragma unroll
        for (int ni = 0; ni < 4; ni++) {
            int r = bm + wm + mi * 16 + gid;
            int c = bn + wn + ni * 8 + tig * 2;
            float b0 = 0.f, b1 = 0.f;
            if (bias) { b0 = bias[c]; b1 = bias[c + 1]; }
            float2 v0 = make_float2(acc[mi][ni][0] + b0, acc[mi][ni][1] + b1);
            float2 v1 = make_float2(acc[mi][ni][2] + b0, acc[mi][ni][3] + b1);
            *(float2*)(C + (size_t)r * N + c)       = v0;
            *(float2*)(C + (size_t)(r + 8) * N + c) = v1;
        }
    }
}

// ---------------- per-pair 2x2 rotation (HLA RoPE in low-rank space) ----------------
__global__ void rotate_kernel(float* __restrict__ x, const float* __restrict__ rot,
                              int M, int halfD, int S)
{
    int idx = blockIdx.x * blockDim.x + threadIdx.x;
    if (idx >= M * halfD) return;
    int m = idx / halfD;
    int p = idx - m * halfD;
    int s = m % S;
    int h = p & 15;
    float4 r = ((const float4*)rot)[s * 16 + h];  // (c, -s, s, c)
    float c = r.x, sn = r.z;
    float* xp = x + (size_t)m * (halfD * 2) + 2 * p;
    float t0 = xp[0], t1 = xp[1];
    xp[0] = t0 * c + t1 * sn;
    xp[1] = t1 * c - t0 * sn;
}

// ---------------- copy first Nsrc columns of each row into dst ----------------
__global__ void copy_cols_kernel(const float* __restrict__ src, float* __restrict__ dst,
                                 int M, int Nsrc, int Ndst)
{
    int idx = blockIdx.x * blockDim.x + threadIdx.x;
    int per_row = Nsrc / 4;
    if (idx >= M * per_row) return;
    int m = idx / per_row;
    int c = idx - m * per_row;
    ((float4*)(dst + (size_t)m * Ndst))[c] = ((const float4*)(src + (size_t)m * Nsrc))[c];
}

// ---------------- causal GQA flash attention (TF32 tensor cores, 64x64 tiles) ----------------
// Q: (B,S,2048) head h at cols [64h,64h+64). K,V: (B,S,512), kv head h>>2.
// 8 warps; warp w owns rows [wm,wm+16) x cols [wn,wn+32) of each 64x64 tile.
#define APAD 68   // 64+4: frag loads (gid*4+tig bank pattern) conflict-free
#define ATT_Q  0
#define ATT_K  (64 * APAD)
#define ATT_V  (2 * 64 * APAD)
#define ATT_S  (3 * 64 * APAD)
#define ATT_ML (ATT_S + 64 * APAD)
#define ATT_SMEM_FLOATS (ATT_ML + 3 * 64)

__global__ __launch_bounds__(256) void attn_kernel(
    const float* __restrict__ Q, const float* __restrict__ Km,
    const float* __restrict__ Vm, float* __restrict__ O, int S)
{
    extern __shared__ float sm[];
    uint32_t* Qs = (uint32_t*)(sm + ATT_Q);   // tf32 bits, [64][APAD]
    uint32_t* Ks = (uint32_t*)(sm + ATT_K);
    uint32_t* Vs = (uint32_t*)(sm + ATT_V);
    float*    Ss = sm + ATT_S;                // fp32 scores/probs, [64][APAD]
    float* m_s     = sm + ATT_ML;
    float* l_s     = m_s + 64;
    float* alpha_s = l_s + 64;

    const int tid  = threadIdx.x;
    const int warp = tid >> 5, lane = tid & 31;
    const int gid  = lane >> 2, tig = lane & 3;
    const int wm = (warp >> 1) * 16;   // 4 row-groups of 16
    const int wn = (warp &  1) * 32;   // 2 col-groups of 32
    const int r0 = wm + gid;

    const int qt = blockIdx.x, h = blockIdx.y, b = blockIdx.z;
    const int hk = h >> 2;

    // load Q tile (scaled, tf32 at store)
    const float* qbase = Q + ((size_t)b * S + qt * 64) * 2048 + h * 64;
    for (int i = tid; i < 64 * 16; i += 256) {
        int r = i >> 4, c = (i & 15) * 4;
        float4 v = *(const float4*)(qbase + (size_t)r * 2048 + c);
        Qs[r * APAD + c + 0] = cvt_tf32(v.x * 0.125f);
        Qs[r * APAD + c + 1] = cvt_tf32(v.y * 0.125f);
        Qs[r * APAD + c + 2] = cvt_tf32(v.z * 0.125f);
        Qs[r * APAD + c + 3] = cvt_tf32(v.w * 0.125f);
    }
    if (tid < 64) { m_s[tid] = -1e30f; l_s[tid] = 0.f; }

    float o_acc[4][4];
#pragma unroll
    for (int ni = 0; ni < 4; ni++)
#pragma unroll
        for (int r = 0; r < 4; r++) o_acc[ni][r] = 0.f;
    __syncthreads();

    const float* kbase = Km + ((size_t)b * S) * 512 + hk * 64;
    const float* vbase = Vm + ((size_t)b * S) * 512 + hk * 64;

    for (int kt = 0; kt <= qt; kt++) {
        // load K,V tiles (tf32 at store)
        for (int i = tid; i < 64 * 16; i += 256) {
            int r = i >> 4, c = (i & 15) * 4;
            float4 kv = *(const float4*)(kbase + (size_t)(kt * 64 + r) * 512 + c);
            Ks[r * APAD + c + 0] = cvt_tf32(kv.x);
            Ks[r * APAD + c + 1] = cvt_tf32(kv.y);
            Ks[r * APAD + c + 2] = cvt_tf32(kv.z);
            Ks[r * APAD + c + 3] = cvt_tf32(kv.w);
            float4 vv = *(const float4*)(vbase + (size_t)(kt * 64 + r) * 512 + c);
            Vs[r * APAD + c + 0] = cvt_tf32(vv.x);
            Vs[r * APAD + c + 1] = cvt_tf32(vv.y);
            Vs[r * APAD + c + 2] = cvt_tf32(vv.z);
            Vs[r * APAD + c + 3] = cvt_tf32(vv.w);
        }
        __syncthreads();

        // ---- S = Q K^T via mma (warp: 16x32 tile = 4 n-tiles) ----
        float sacc[4][4];
#pragma unroll
        for (int ni = 0; ni < 4; ni++)
#pragma unroll
            for (int r = 0; r < 4; r++) sacc[ni][r] = 0.f;
#pragma unroll
        for (int k8 = 0; k8 < 64; k8 += 8) {
            uint32_t af[4], bf[4][2];
            af[0] = Qs[(r0    ) * APAD + k8 + tig    ];
            af[1] = Qs[(r0 + 8) * APAD + k8 + tig    ];
            af[2] = Qs[(r0    ) * APAD + k8 + tig + 4];
            af[3] = Qs[(r0 + 8) * APAD + k8 + tig + 4];
#pragma unroll
            for (int ni = 0; ni < 4; ni++) {
                int n0 = wn + ni * 8 + gid;           // key index (NT layout)
                bf[ni][0] = Ks[n0 * APAD + k8 + tig    ];
                bf[ni][1] = Ks[n0 * APAD + k8 + tig + 4];
            }
#pragma unroll
            for (int ni = 0; ni < 4; ni++)
                mma_tf32(sacc[ni], af, bf[ni]);
        }
        // causal mask on the diagonal tile
        if (kt == qt) {
#pragma unroll
            for (int ni = 0; ni < 4; ni++) {
                int c0 = wn + ni * 8 + tig * 2;
                if (c0     > r0    ) sacc[ni][0] = -1e30f;
                if (c0 + 1 > r0    ) sacc[ni][1] = -1e30f;
                if (c0     > r0 + 8) sacc[ni][2] = -1e30f;
                if (c0 + 1 > r0 + 8) sacc[ni][3] = -1e30f;
            }
        }
        // accumulators -> Ss
#pragma unroll
        for (int ni = 0; ni < 4; ni++) {
            int c0 = wn + ni * 8 + tig * 2;
            Ss[(r0    ) * APAD + c0    ] = sacc[ni][0];
            Ss[(r0    ) * APAD + c0 + 1] = sacc[ni][1];
            Ss[(r0 + 8) * APAD + c0    ] = sacc[ni][2];
            Ss[(r0 + 8) * APAD + c0 + 1] = sacc[ni][3];
        }
        __syncthreads();

        // ---- online softmax (4 threads per row, 16 cols each) ----
        {
            int row = tid >> 2, seg = tid & 3;
            int c0 = seg * 16;
            float mloc = -1e30f;
#pragma unroll
            for (int c = 0; c < 16; c++) mloc = fmaxf(mloc, Ss[row * APAD + c0 + c]);
            mloc = fmaxf(mloc, __shfl_xor_sync(0xffffffffu, mloc, 1));
            mloc = fmaxf(mloc, __shfl_xor_sync(0xffffffffu, mloc, 2));
            float mold = m_s[row];
            float mnew = fmaxf(mold, mloc);
            float lsum = 0.f;
#pragma unroll
            for (int c = 0; c < 16; c++) {
                float p = __expf(Ss[row * APAD + c0 + c] - mnew);
                Ss[row * APAD + c0 + c] = p;
                lsum += p;
            }
            lsum += __shfl_xor_sync(0xffffffffu, lsum, 1);
            lsum += __shfl_xor_sync(0xffffffffu, lsum, 2);
            if (seg == 0) {
                float alpha = __expf(mold - mnew);
                m_s[row] = mnew;
                l_s[row] = l_s[row] * alpha + lsum;
                alpha_s[row] = alpha;
            }
        }
        __syncthreads();

        // ---- O = O*alpha + P V via mma ----
        {
            float a0 = alpha_s[r0], a1 = alpha_s[r0 + 8];
#pragma unroll
            for (int ni = 0; ni < 4; ni++) {
                o_acc[ni][0] *= a0; o_acc[ni][1] *= a0;
                o_acc[ni][2] *= a1; o_acc[ni][3] *= a1;
            }
        }
#pragma unroll
        for (int k8 = 0; k8 < 64; k8 += 8) {
            uint32_t af[4], bf[4][2];
            af[0] = cvt_tf32(Ss[(r0    ) * APAD + k8 + tig    ]);
            af[1] = cvt_tf32(Ss[(r0 + 8) * APAD + k8 + tig    ]);
            af[2] = cvt_tf32(Ss[(r0    ) * APAD + k8 + tig + 4]);
            af[3] = cvt_tf32(Ss[(r0 + 8) * APAD + k8 + tig + 4]);
#pragma unroll
            for (int ni = 0; ni < 4; ni++) {
                int n0 = wn + ni * 8 + gid;           // d index (NN layout: Vs[key][d])
                bf[ni][0] = Vs[(k8 + tig    ) * APAD + n0];
                bf[ni][1] = Vs[(k8 + tig + 4) * APAD + n0];
            }
#pragma unroll
            for (int ni = 0; ni < 4; ni++)
                mma_tf32(o_acc[ni], af, bf[ni]);
        }
        __syncthreads();
    }

    // ---- epilogue: divide by l, write ----
    float* obase = O + ((size_t)b * S + qt * 64) * 2048 + h * 64;
    float li0 = 1.f / l_s[r0], li1 = 1.f / l_s[r0 + 8];
#pragma unroll
    for (int ni = 0; ni < 4; ni++) {
        int c = wn + ni * 8 + tig * 2;
        float2 v0 = make_float2(o_acc[ni][0] * li0, o_acc[ni][1] * li0);
        float2 v1 = make_float2(o_acc[ni][2] * li1, o_acc[ni][3] * li1);
        *(float2*)(obase + (size_t)(r0    ) * 2048 + c) = v0;
        *(float2*)(obase + (size_t)(r0 + 8) * 2048 + c) = v1;
    }
}

// ---------------- launch helpers ----------------
static inline void gemmNT(const float* A, const float* B, const float* bias,
                          float* C, int M, int N, int K) {
    dim3 g(N / 128, M / 128);
    cudaFuncSetAttribute(tf32_gemm_kernel<true>,
                         cudaFuncAttributeMaxDynamicSharedMemorySize, GEMM_SMEM_BYTES);
    tf32_gemm_kernel<true><<<g, 256, GEMM_SMEM_BYTES>>>(A, B, bias, C, M, N, K);
}
static inline void gemmNN(const float* A, const float* B, const float* bias,
                          float* C, int M, int N, int K) {
    dim3 g(N / 128, M / 128);
    cudaFuncSetAttribute(tf32_gemm_kernel<false>,
                         cudaFuncAttributeMaxDynamicSharedMemorySize, GEMM_SMEM_BYTES);
    tf32_gemm_kernel<false><<<g, 256, GEMM_SMEM_BYTES>>>(A, B, bias, C, M, N, K);
}

extern "C" void kernel_launch(void* const* d_in, const int* in_sizes, int n_in,
                              void* d_out, int out_size)
{
    (void)n_in; (void)out_size;
    const float* X   = (const float*)d_in[0];
    const float* rot = (const float*)d_in[1];
    // d_in[2] = mask: exactly causal -> handled analytically in attn_kernel
    const float* Wqd = (const float*)d_in[3];
    const float* bqd = (const float*)d_in[4];
    const float* Wqu = (const float*)d_in[5];
    const float* bqu = (const float*)d_in[6];
    const float* Wkd = (const float*)d_in[7];
    const float* bkd = (const float*)d_in[8];
    const float* Wku = (const float*)d_in[9];
    const float* bku = (const float*)d_in[10];
    const float* Wvd = (const float*)d_in[11];
    const float* bvd = (const float*)d_in[12];
    const float* Wvu = (const float*)d_in[13];
    const float* bvu = (const float*)d_in[14];
    const float* Wo  = (const float*)d_in[15];
    const float* B_q = (const float*)d_in[16];
    const float* B_k = (const float*)d_in[17];
    const float* C_q = (const float*)d_in[18];
    const float* C_k = (const float*)d_in[19];
    float* out = (float*)d_out;

    const int S = in_sizes[1] / 64;          // rot is (S,16,2,2)
    const int M = in_sizes[0] / 2048;        // tokens = B*S
    const int Bb = M / S;

    float *qh, *tq, *Qb, *kh, *tk, *Kb, *vh, *Vb, *Ob;
    cudaGetSymbolAddress((void**)&qh, g_qh);
    cudaGetSymbolAddress((void**)&tq, g_tq);
    cudaGetSymbolAddress((void**)&Qb, g_Q);
    cudaGetSymbolAddress((void**)&kh, g_kh);
    cudaGetSymbolAddress((void**)&tk, g_tk);
    cudaGetSymbolAddress((void**)&Kb, g_K);
    cudaGetSymbolAddress((void**)&vh, g_vh);
    cudaGetSymbolAddress((void**)&Vb, g_V);
    cudaGetSymbolAddress((void**)&Ob, g_O);

    // ---- Q path ----
    gemmNT(X, Wqd, bqd, qh, M, 1024, 2048);                 // qh = X Wqd^T + b
    gemmNT(qh, B_q, nullptr, tq, M, 1024, 1024);            // t = qh B_q^T
    rotate_kernel<<<(M * 512 + 255) / 256, 256>>>(tq, rot, M, 512, S);
    gemmNN(tq, B_q, nullptr, qh, M, 1024, 1024);            // qh = u B_q
    gemmNT(qh, Wqu, bqu, Qb, M, 2048, 1024);                // Q = qh Wqu^T + b
    gemmNN(Qb, C_q, nullptr, tq, M, 1024, 2048);            // Qc = Q C_q
    copy_cols_kernel<<<(M * 256 + 255) / 256, 256>>>(tq, Qb, M, 1024, 2048);

    // ---- K path ----
    gemmNT(X, Wkd, bkd, kh, M, 256, 2048);
    gemmNT(kh, B_k, nullptr, tk, M, 256, 256);
    rotate_kernel<<<(M * 128 + 255) / 256, 256>>>(tk, rot, M, 128, S);
    gemmNN(tk, B_k, nullptr, kh, M, 256, 256);
    gemmNT(kh, Wku, bku, Kb, M, 512, 256);
    gemmNN(Kb, C_k, nullptr, tk, M, 256, 512);
    copy_cols_kernel<<<(M * 64 + 255) / 256, 256>>>(tk, Kb, M, 256, 512);

    // ---- V path ----
    gemmNT(X, Wvd, bvd, vh, M, 256, 2048);
    gemmNT(vh, Wvu, bvu, Vb, M, 512, 256);

    // ---- attention ----
    const int att_smem = ATT_SMEM_FLOATS * (int)sizeof(float);
    cudaFuncSetAttribute(attn_kernel, cudaFuncAttributeMaxDynamicSharedMemorySize, att_smem);
    attn_kernel<<<dim3(S / 64, 32, Bb), 256, att_smem>>>(Qb, Kb, Vb, Ob, S);

    // ---- output projection ----
    gemmNT(Ob, Wo, nullptr, out, M, 2048, 2048);
}

// round 9
// speedup vs baseline: 3.8936x; 1.0677x over previous
#include <cuda_runtime.h>
#include <cstdint>
#include <cstddef>

// ---------------- scratch (device globals; no allocation allowed) ----------------
__device__ float g_qh[2048 * 1024];
__device__ float g_tq[2048 * 1024];
__device__ float g_Q [2048 * 2048];
__device__ float g_kh[2048 * 256];
__device__ float g_tk[2048 * 256];
__device__ float g_K [2048 * 512];
__device__ float g_vh[2048 * 256];
__device__ float g_V [2048 * 512];
__device__ float g_O [2048 * 2048];

// ---------------- shared PTX helpers ----------------
__device__ __forceinline__ uint32_t cvt_tf32(float x) {
    uint32_t r;
    asm("cvt.rna.tf32.f32 %0, %1;" : "=r"(r) : "f"(x));
    return r;
}

__device__ __forceinline__ void mma_tf32(float* c, const uint32_t* a, const uint32_t* b) {
    asm volatile(
        "mma.sync.aligned.m16n8k8.row.col.f32.tf32.tf32.f32 "
        "{%0,%1,%2,%3}, {%4,%5,%6,%7}, {%8,%9}, {%0,%1,%2,%3};"
        : "+f"(c[0]), "+f"(c[1]), "+f"(c[2]), "+f"(c[3])
        : "r"(a[0]), "r"(a[1]), "r"(a[2]), "r"(a[3]), "r"(b[0]), "r"(b[1]));
}

__device__ __forceinline__ void cp_async16(uint32_t smem_dst, const void* gsrc) {
    asm volatile("cp.async.ca.shared.global [%0], [%1], 16;\n"
                 :: "r"(smem_dst), "l"(gsrc));
}
__device__ __forceinline__ void cp_commit() {
    asm volatile("cp.async.commit_group;\n");
}
template <int N>
__device__ __forceinline__ void cp_wait() {
    asm volatile("cp.async.wait_group %0;\n" :: "n"(N));
}

// ---------------- TF32 tensor-core GEMM (templated tiles, 2-stage cp.async) ----------------
// C[m,n] = sum_k A[m,k] * (TRANSB ? B[n,k] : B[k,n]) + bias[n]
// 256 threads, 8 warps in WMG x WNG grid; warp tile (BM/WMG) x (BN/WNG).
// Requires M%BM==0, N%BN==0, K%32==0.
#define KT   32
#define SPAD 36    // n-major row stride (floats): frag loads conflict-free

template <bool TRANSB, int BM, int BN>
__device__ __forceinline__ void gemm_load_tiles(
    float* base, const float* A, const float* B,
    int bm, int bn, int k0, int K, int N, int tid)
{
    constexpr int NPADL = BN + 4;
    constexpr int ASZL  = BM * SPAD;
    constexpr int NNROW = BN / 4;        // float4s per NN row
    constexpr int NNSTEP = 256 / NNROW;  // k-rows per load iter

    float* As = base;
    float* Bs = base + ASZL;
    const int lr = tid >> 3, lc = (tid & 7) * 4;
#pragma unroll
    for (int i = 0; i < BM / 32; i++) {
        int r = lr + i * 32;
        uint32_t dst = (uint32_t)__cvta_generic_to_shared(As + r * SPAD + lc);
        cp_async16(dst, A + (size_t)(bm + r) * K + k0 + lc);
    }
    if (TRANSB) {
#pragma unroll
        for (int i = 0; i < BN / 32; i++) {
            int r = lr + i * 32;
            uint32_t dst = (uint32_t)__cvta_generic_to_shared(Bs + r * SPAD + lc);
            cp_async16(dst, B + (size_t)(bn + r) * K + k0 + lc);
        }
    } else {
        const int lk = tid / NNROW, ln = (tid % NNROW) * 4;
#pragma unroll
        for (int i = 0; i < BN / 32; i++) {
            int k = lk + i * NNSTEP;
            uint32_t dst = (uint32_t)__cvta_generic_to_shared(Bs + k * NPADL + ln);
            cp_async16(dst, B + (size_t)(k0 + k) * N + bn + ln);
        }
    }
    cp_commit();
}

template <bool TRANSB, int BM, int BN, int WMG, int WNG>
__global__ __launch_bounds__(256)
void tf32_gemm_kernel(const float* __restrict__ A, const float* __restrict__ B,
                      const float* __restrict__ bias, float* __restrict__ C,
                      int M, int N, int K)
{
    constexpr int WTM = BM / WMG, WTN = BN / WNG;
    constexpr int MI = WTM / 16, NI = WTN / 8;
    constexpr int NPADL = BN + 4;
    constexpr int ASZL  = BM * SPAD;
    constexpr int BSZL  = TRANSB ? BN * SPAD : KT * NPADL;
    constexpr int STAGEL = ASZL + BSZL;

    extern __shared__ float smem[];

    const int tid  = threadIdx.x;
    const int warp = tid >> 5, lane = tid & 31;
    const int gid  = lane >> 2, tig = lane & 3;
    const int bm = blockIdx.y * BM, bn = blockIdx.x * BN;
    const int wm = (warp / WNG) * WTM;
    const int wn = (warp % WNG) * WTN;

    float acc[MI][NI][4];
#pragma unroll
    for (int mi = 0; mi < MI; mi++)
#pragma unroll
        for (int ni = 0; ni < NI; ni++)
#pragma unroll
            for (int r = 0; r < 4; r++) acc[mi][ni][r] = 0.f;

    gemm_load_tiles<TRANSB, BM, BN>(smem, A, B, bm, bn, 0, K, N, tid);

    int s = 0;
    for (int k0 = 0; k0 < K; k0 += KT, s ^= 1) {
        if (k0 + KT < K) {
            gemm_load_tiles<TRANSB, BM, BN>(smem + (s ^ 1) * STAGEL, A, B,
                                            bm, bn, k0 + KT, K, N, tid);
            cp_wait<1>();
        } else {
            cp_wait<0>();
        }
        __syncthreads();

        const float* As = smem + s * STAGEL;
        const float* Bs = As + ASZL;
#pragma unroll
        for (int k8 = 0; k8 < KT; k8 += 8) {
            uint32_t af[MI][4], bf[NI][2];
#pragma unroll
            for (int mi = 0; mi < MI; mi++) {
                int r0 = wm + mi * 16 + gid;
                af[mi][0] = cvt_tf32(As[(r0    ) * SPAD + k8 + tig    ]);
                af[mi][1] = cvt_tf32(As[(r0 + 8) * SPAD + k8 + tig    ]);
                af[mi][2] = cvt_tf32(As[(r0    ) * SPAD + k8 + tig + 4]);
                af[mi][3] = cvt_tf32(As[(r0 + 8) * SPAD + k8 + tig + 4]);
            }
#pragma unroll
            for (int ni = 0; ni < NI; ni++) {
                int n0 = wn + ni * 8 + gid;
                if (TRANSB) {
                    bf[ni][0] = cvt_tf32(Bs[n0 * SPAD + k8 + tig    ]);
                    bf[ni][1] = cvt_tf32(Bs[n0 * SPAD + k8 + tig + 4]);
                } else {
                    bf[ni][0] = cvt_tf32(Bs[(k8 + tig    ) * NPADL + n0]);
                    bf[ni][1] = cvt_tf32(Bs[(k8 + tig + 4) * NPADL + n0]);
                }
            }
#pragma unroll
            for (int mi = 0; mi < MI; mi++)
#pragma unroll
                for (int ni = 0; ni < NI; ni++)
                    mma_tf32(acc[mi][ni], af[mi], bf[ni]);
        }
        __syncthreads();
    }

    // --- epilogue: bias + store (float2 per mma row) ---
#pragma unroll
    for (int mi = 0; mi < MI; mi++) {
#pragma unroll
        for (int ni = 0; ni < NI; ni++) {
            int r = bm + wm + mi * 16 + gid;
            int c = bn + wn + ni * 8 + tig * 2;
            float b0 = 0.f, b1 = 0.f;
            if (bias) { b0 = bias[c]; b1 = bias[c + 1]; }
            float2 v0 = make_float2(acc[mi][ni][0] + b0, acc[mi][ni][1] + b1);
            float2 v1 = make_float2(acc[mi][ni][2] + b0, acc[mi][ni][3] + b1);
            *(float2*)(C + (size_t)r * N + c)       = v0;
            *(float2*)(C + (size_t)(r + 8) * N + c) = v1;
        }
    }
}

// ---------------- per-pair 2x2 rotation (HLA RoPE in low-rank space) ----------------
__global__ void rotate_kernel(float* __restrict__ x, const float* __restrict__ rot,
                              int M, int halfD, int S)
{
    int idx = blockIdx.x * blockDim.x + threadIdx.x;
    if (idx >= M * halfD) return;
    int m = idx / halfD;
    int p = idx - m * halfD;
    int s = m % S;
    int h = p & 15;
    float4 r = ((const float4*)rot)[s * 16 + h];  // (c, -s, s, c)
    float c = r.x, sn = r.z;
    float* xp = x + (size_t)m * (halfD * 2) + 2 * p;
    float t0 = xp[0], t1 = xp[1];
    xp[0] = t0 * c + t1 * sn;
    xp[1] = t1 * c - t0 * sn;
}

// ---------------- copy first Nsrc columns of each row into dst ----------------
__global__ void copy_cols_kernel(const float* __restrict__ src, float* __restrict__ dst,
                                 int M, int Nsrc, int Ndst)
{
    int idx = blockIdx.x * blockDim.x + threadIdx.x;
    int per_row = Nsrc / 4;
    if (idx >= M * per_row) return;
    int m = idx / per_row;
    int c = idx - m * per_row;
    ((float4*)(dst + (size_t)m * Ndst))[c] = ((const float4*)(src + (size_t)m * Nsrc))[c];
}

// ---------------- causal GQA flash attention (TF32 tensor cores, 64x64 tiles) ----------------
#define APAD 68
#define ATT_Q  0
#define ATT_K  (64 * APAD)
#define ATT_V  (2 * 64 * APAD)
#define ATT_S  (3 * 64 * APAD)
#define ATT_ML (ATT_S + 64 * APAD)
#define ATT_SMEM_FLOATS (ATT_ML + 3 * 64)

__global__ __launch_bounds__(256) void attn_kernel(
    const float* __restrict__ Q, const float* __restrict__ Km,
    const float* __restrict__ Vm, float* __restrict__ O, int S)
{
    extern __shared__ float sm[];
    uint32_t* Qs = (uint32_t*)(sm + ATT_Q);
    uint32_t* Ks = (uint32_t*)(sm + ATT_K);
    uint32_t* Vs = (uint32_t*)(sm + ATT_V);
    float*    Ss = sm + ATT_S;
    float* m_s     = sm + ATT_ML;
    float* l_s     = m_s + 64;
    float* alpha_s = l_s + 64;

    const int tid  = threadIdx.x;
    const int warp = tid >> 5, lane = tid & 31;
    const int gid  = lane >> 2, tig = lane & 3;
    const int wm = (warp >> 1) * 16;
    const int wn = (warp &  1) * 32;
    const int r0 = wm + gid;

    const int qt = blockIdx.x, h = blockIdx.y, b = blockIdx.z;
    const int hk = h >> 2;

    const float* qbase = Q + ((size_t)b * S + qt * 64) * 2048 + h * 64;
    for (int i = tid; i < 64 * 16; i += 256) {
        int r = i >> 4, c = (i & 15) * 4;
        float4 v = *(const float4*)(qbase + (size_t)r * 2048 + c);
        Qs[r * APAD + c + 0] = cvt_tf32(v.x * 0.125f);
        Qs[r * APAD + c + 1] = cvt_tf32(v.y * 0.125f);
        Qs[r * APAD + c + 2] = cvt_tf32(v.z * 0.125f);
        Qs[r * APAD + c + 3] = cvt_tf32(v.w * 0.125f);
    }
    if (tid < 64) { m_s[tid] = -1e30f; l_s[tid] = 0.f; }

    float o_acc[4][4];
#pragma unroll
    for (int ni = 0; ni < 4; ni++)
#pragma unroll
        for (int r = 0; r < 4; r++) o_acc[ni][r] = 0.f;
    __syncthreads();

    const float* kbase = Km + ((size_t)b * S) * 512 + hk * 64;
    const float* vbase = Vm + ((size_t)b * S) * 512 + hk * 64;

    for (int kt = 0; kt <= qt; kt++) {
        for (int i = tid; i < 64 * 16; i += 256) {
            int r = i >> 4, c = (i & 15) * 4;
            float4 kv = *(const float4*)(kbase + (size_t)(kt * 64 + r) * 512 + c);
            Ks[r * APAD + c + 0] = cvt_tf32(kv.x);
            Ks[r * APAD + c + 1] = cvt_tf32(kv.y);
            Ks[r * APAD + c + 2] = cvt_tf32(kv.z);
            Ks[r * APAD + c + 3] = cvt_tf32(kv.w);
            float4 vv = *(const float4*)(vbase + (size_t)(kt * 64 + r) * 512 + c);
            Vs[r * APAD + c + 0] = cvt_tf32(vv.x);
            Vs[r * APAD + c + 1] = cvt_tf32(vv.y);
            Vs[r * APAD + c + 2] = cvt_tf32(vv.z);
            Vs[r * APAD + c + 3] = cvt_tf32(vv.w);
        }
        __syncthreads();

        float sacc[4][4];
#pragma unroll
        for (int ni = 0; ni < 4; ni++)
#pragma unroll
            for (int r = 0; r < 4; r++) sacc[ni][r] = 0.f;
#pragma unroll
        for (int k8 = 0; k8 < 64; k8 += 8) {
            uint32_t af[4], bf[4][2];
            af[0] = Qs[(r0    ) * APAD + k8 + tig    ];
            af[1] = Qs[(r0 + 8) * APAD + k8 + tig    ];
            af[2] = Qs[(r0    ) * APAD + k8 + tig + 4];
            af[3] = Qs[(r0 + 8) * APAD + k8 + tig + 4];
#pragma unroll
            for (int ni = 0; ni < 4; ni++) {
                int n0 = wn + ni * 8 + gid;
                bf[ni][0] = Ks[n0 * APAD + k8 + tig    ];
                bf[ni][1] = Ks[n0 * APAD + k8 + tig + 4];
            }
#pragma unroll
            for (int ni = 0; ni < 4; ni++)
                mma_tf32(sacc[ni], af, bf[ni]);
        }
        if (kt == qt) {
#pragma unroll
            for (int ni = 0; ni < 4; ni++) {
                int c0 = wn + ni * 8 + tig * 2;
                if (c0     > r0    ) sacc[ni][0] = -1e30f;
                if (c0 + 1 > r0    ) sacc[ni][1] = -1e30f;
                if (c0     > r0 + 8) sacc[ni][2] = -1e30f;
                if (c0 + 1 > r0 + 8) sacc[ni][3] = -1e30f;
            }
        }
#pragma unroll
        for (int ni = 0; ni < 4; ni++) {
            int c0 = wn + ni * 8 + tig * 2;
            Ss[(r0    ) * APAD + c0    ] = sacc[ni][0];
            Ss[(r0    ) * APAD + c0 + 1] = sacc[ni][1];
            Ss[(r0 + 8) * APAD + c0    ] = sacc[ni][2];
            Ss[(r0 + 8) * APAD + c0 + 1] = sacc[ni][3];
        }
        __syncthreads();

        {
            int row = tid >> 2, seg = tid & 3;
            int c0 = seg * 16;
            float mloc = -1e30f;
#pragma unroll
            for (int c = 0; c < 16; c++) mloc = fmaxf(mloc, Ss[row * APAD + c0 + c]);
            mloc = fmaxf(mloc, __shfl_xor_sync(0xffffffffu, mloc, 1));
            mloc = fmaxf(mloc, __shfl_xor_sync(0xffffffffu, mloc, 2));
            float mold = m_s[row];
            float mnew = fmaxf(mold, mloc);
            float lsum = 0.f;
#pragma unroll
            for (int c = 0; c < 16; c++) {
                float p = __expf(Ss[row * APAD + c0 + c] - mnew);
                Ss[row * APAD + c0 + c] = p;
                lsum += p;
            }
            lsum += __shfl_xor_sync(0xffffffffu, lsum, 1);
            lsum += __shfl_xor_sync(0xffffffffu, lsum, 2);
            if (seg == 0) {
                float alpha = __expf(mold - mnew);
                m_s[row] = mnew;
                l_s[row] = l_s[row] * alpha + lsum;
                alpha_s[row] = alpha;
            }
        }
        __syncthreads();

        {
            float a0 = alpha_s[r0], a1 = alpha_s[r0 + 8];
#pragma unroll
            for (int ni = 0; ni < 4; ni++) {
                o_acc[ni][0] *= a0; o_acc[ni][1] *= a0;
                o_acc[ni][2] *= a1; o_acc[ni][3] *= a1;
            }
        }
#pragma unroll
        for (int k8 = 0; k8 < 64; k8 += 8) {
            uint32_t af[4], bf[4][2];
            af[0] = cvt_tf32(Ss[(r0    ) * APAD + k8 + tig    ]);
            af[1] = cvt_tf32(Ss[(r0 + 8) * APAD + k8 + tig    ]);
            af[2] = cvt_tf32(Ss[(r0    ) * APAD + k8 + tig + 4]);
            af[3] = cvt_tf32(Ss[(r0 + 8) * APAD + k8 + tig + 4]);
#pragma unroll
            for (int ni = 0; ni < 4; ni++) {
                int n0 = wn + ni * 8 + gid;
                bf[ni][0] = Vs[(k8 + tig    ) * APAD + n0];
                bf[ni][1] = Vs[(k8 + tig + 4) * APAD + n0];
            }
#pragma unroll
            for (int ni = 0; ni < 4; ni++)
                mma_tf32(o_acc[ni], af, bf[ni]);
        }
        __syncthreads();
    }

    float* obase = O + ((size_t)b * S + qt * 64) * 2048 + h * 64;
    float li0 = 1.f / l_s[r0], li1 = 1.f / l_s[r0 + 8];
#pragma unroll
    for (int ni = 0; ni < 4; ni++) {
        int c = wn + ni * 8 + tig * 2;
        float2 v0 = make_float2(o_acc[ni][0] * li0, o_acc[ni][1] * li0);
        float2 v1 = make_float2(o_acc[ni][2] * li1, o_acc[ni][3] * li1);
        *(float2*)(obase + (size_t)(r0    ) * 2048 + c) = v0;
        *(float2*)(obase + (size_t)(r0 + 8) * 2048 + c) = v1;
    }
}

// ---------------- launch helpers ----------------
template <bool TRANSB, int BM, int BN, int WMG, int WNG>
static inline void gemm_run(const float* A, const float* B, const float* bias,
                            float* C, int M, int N, int K) {
    constexpr int SMEMB = 2 * (BM * SPAD + (TRANSB ? BN * SPAD : KT * (BN + 4))) * 4;
    dim3 g(N / BN, M / BM);
    cudaFuncSetAttribute(tf32_gemm_kernel<TRANSB, BM, BN, WMG, WNG>,
                         cudaFuncAttributeMaxDynamicSharedMemorySize, SMEMB);
    tf32_gemm_kernel<TRANSB, BM, BN, WMG, WNG><<<g, 256, SMEMB>>>(A, B, bias, C, M, N, K);
}
static inline void gemmNT(const float* A, const float* B, const float* bias,
                          float* C, int M, int N, int K) {
    if (N >= 1024) gemm_run<true, 128, 64, 4, 2>(A, B, bias, C, M, N, K);
    else           gemm_run<true,  64, 64, 4, 2>(A, B, bias, C, M, N, K);
}
static inline void gemmNN(const float* A, const float* B, const float* bias,
                          float* C, int M, int N, int K) {
    if (N >= 1024) gemm_run<false, 128, 64, 4, 2>(A, B, bias, C, M, N, K);
    else           gemm_run<false,  64, 64, 4, 2>(A, B, bias, C, M, N, K);
}

extern "C" void kernel_launch(void* const* d_in, const int* in_sizes, int n_in,
                              void* d_out, int out_size)
{
    (void)n_in; (void)out_size;
    const float* X   = (const float*)d_in[0];
    const float* rot = (const float*)d_in[1];
    // d_in[2] = mask: exactly causal -> handled analytically in attn_kernel
    const float* Wqd = (const float*)d_in[3];
    const float* bqd = (const float*)d_in[4];
    const float* Wqu = (const float*)d_in[5];
    const float* bqu = (const float*)d_in[6];
    const float* Wkd = (const float*)d_in[7];
    const float* bkd = (const float*)d_in[8];
    const float* Wku = (const float*)d_in[9];
    const float* bku = (const float*)d_in[10];
    const float* Wvd = (const float*)d_in[11];
    const float* bvd = (const float*)d_in[12];
    const float* Wvu = (const float*)d_in[13];
    const float* bvu = (const float*)d_in[14];
    const float* Wo  = (const float*)d_in[15];
    const float* B_q = (const float*)d_in[16];
    const float* B_k = (const float*)d_in[17];
    const float* C_q = (const float*)d_in[18];
    const float* C_k = (const float*)d_in[19];
    float* out = (float*)d_out;

    const int S = in_sizes[1] / 64;          // rot is (S,16,2,2)
    const int M = in_sizes[0] / 2048;        // tokens = B*S
    const int Bb = M / S;

    float *qh, *tq, *Qb, *kh, *tk, *Kb, *vh, *Vb, *Ob;
    cudaGetSymbolAddress((void**)&qh, g_qh);
    cudaGetSymbolAddress((void**)&tq, g_tq);
    cudaGetSymbolAddress((void**)&Qb, g_Q);
    cudaGetSymbolAddress((void**)&kh, g_kh);
    cudaGetSymbolAddress((void**)&tk, g_tk);
    cudaGetSymbolAddress((void**)&Kb, g_K);
    cudaGetSymbolAddress((void**)&vh, g_vh);
    cudaGetSymbolAddress((void**)&Vb, g_V);
    cudaGetSymbolAddress((void**)&Ob, g_O);

    // ---- Q path ----
    gemmNT(X, Wqd, bqd, qh, M, 1024, 2048);                 // qh = X Wqd^T + b
    gemmNT(qh, B_q, nullptr, tq, M, 1024, 1024);            // t = qh B_q^T
    rotate_kernel<<<(M * 512 + 255) / 256, 256>>>(tq, rot, M, 512, S);
    gemmNN(tq, B_q, nullptr, qh, M, 1024, 1024);            // qh = u B_q
    gemmNT(qh, Wqu, bqu, Qb, M, 2048, 1024);                // Q = qh Wqu^T + b
    gemmNN(Qb, C_q, nullptr, tq, M, 1024, 2048);            // Qc = Q C_q
    copy_cols_kernel<<<(M * 256 + 255) / 256, 256>>>(tq, Qb, M, 1024, 2048);

    // ---- K path ----
    gemmNT(X, Wkd, bkd, kh, M, 256, 2048);
    gemmNT(kh, B_k, nullptr, tk, M, 256, 256);
    rotate_kernel<<<(M * 128 + 255) / 256, 256>>>(tk, rot, M, 128, S);
    gemmNN(tk, B_k, nullptr, kh, M, 256, 256);
    gemmNT(kh, Wku, bku, Kb, M, 512, 256);
    gemmNN(Kb, C_k, nullptr, tk, M, 256, 512);
    copy_cols_kernel<<<(M * 64 + 255) / 256, 256>>>(tk, Kb, M, 256, 512);

    // ---- V path ----
    gemmNT(X, Wvd, bvd, vh, M, 256, 2048);
    gemmNT(vh, Wvu, bvu, Vb, M, 512, 256);

    // ---- attention ----
    const int att_smem = ATT_SMEM_FLOATS * (int)sizeof(float);
    cudaFuncSetAttribute(attn_kernel, cudaFuncAttributeMaxDynamicSharedMemorySize, att_smem);
    attn_kernel<<<dim3(S / 64, 32, Bb), 256, att_smem>>>(Qb, Kb, Vb, Ob, S);

    // ---- output projection ----
    gemmNT(Ob, Wo, nullptr, out, M, 2048, 2048);
}